// round 5
// baseline (speedup 1.0000x reference)
#include <cuda_runtime.h>
#include <cuda_bf16.h>
#include <math.h>

// ---------------------------------------------------------------------------
// Problem constants
// ---------------------------------------------------------------------------
#define NQ      6000
#define NBOX    3000
#define KMAX    80
#define CAP     256
#define KS      4
#define NCELL   64
#define RADIUS  0.1125f

#define GDIM    8
#define NCELLS  (GDIM*GDIM*GDIM)

// ---------------------------------------------------------------------------
// Device scratch
// ---------------------------------------------------------------------------
__device__ __align__(16) float g_S[(size_t)NQ * (64 * 96 + 96)];   // rows up to 6240
__device__ __align__(16) float g_x96[NQ * 96];
__device__ __align__(16) float g_ya[NQ * 64];
__device__ __align__(16) float g_yb[NQ * 64];
__device__ __align__(16) float g_part[2 * NQ * 64];
__device__ __align__(16) float g_ff[NQ * 4];

__device__ int   g_fcnt[NQ];
__device__ int   g_fidx[NQ * KMAX];
__device__ int   g_fcell[NQ * KMAX];
__device__ __align__(16) float g_fcoef[(size_t)NQ * KMAX * 8];

__device__ int   g_ocnt[NQ];
__device__ int   g_oidx[NQ * KMAX];
__device__ int   g_ocell[NQ * KMAX];
__device__ __align__(16) float g_ocoef[(size_t)NQ * KMAX * 8];

__device__ int g_gcnt[2][NCELLS];
__device__ int g_gstart[2][NCELLS + 1];
__device__ int g_gcur[2][NCELLS];
__device__ int g_glistF[NQ];
__device__ int g_glistB[NBOX];

// ---------------------------------------------------------------------------
// Helpers
// ---------------------------------------------------------------------------
__device__ __forceinline__ float2 ffma2(float2 a, float2 b, float2 c) {
    float2 d;
    asm("{\n\t"
        ".reg .b64 ra, rb, rc;\n\t"
        "mov.b64 ra, {%2, %3};\n\t"
        "mov.b64 rb, {%4, %5};\n\t"
        "mov.b64 rc, {%6, %7};\n\t"
        "fma.rn.f32x2 rc, ra, rb, rc;\n\t"
        "mov.b64 {%0, %1}, rc;\n\t"
        "}"
        : "=f"(d.x), "=f"(d.y)
        : "f"(a.x), "f"(a.y), "f"(b.x), "f"(b.y), "f"(c.x), "f"(c.y));
    return d;
}

__device__ __forceinline__ float fsign(float x) {
    return (x > 0.f) ? 1.f : ((x < 0.f) ? -1.f : 0.f);
}

__device__ __forceinline__ int cell_coord(float x) {
    int c = (int)(x * (float)GDIM);
    return min(max(c, 0), GDIM - 1);
}

// ---------------------------------------------------------------------------
// prep: ff = [1,vel]; x96[:,64:96] = ff @ d0_w + d0_b; zero grid counters
// ---------------------------------------------------------------------------
__global__ void prep_kernel(const float* __restrict__ vel,
                            const float* __restrict__ d0_w, const float* __restrict__ d0_b) {
    int i = blockIdx.x * blockDim.x + threadIdx.x;
    if (i < 2 * NCELLS) g_gcnt[0][i] = 0;   // covers both [2][NCELLS]
    if (i >= NQ) return;
    float f1 = vel[i * 3 + 0], f2 = vel[i * 3 + 1], f3 = vel[i * 3 + 2];
    g_ff[i * 4 + 0] = 1.0f;
    g_ff[i * 4 + 1] = f1;
    g_ff[i * 4 + 2] = f2;
    g_ff[i * 4 + 3] = f3;
    #pragma unroll 8
    for (int o = 0; o < 32; o++) {
        g_x96[i * 96 + 64 + o] = d0_w[o] + f1 * d0_w[32 + o] + f2 * d0_w[64 + o]
                                 + f3 * d0_w[96 + o] + d0_b[o];
    }
}

// ---------------------------------------------------------------------------
// Hash grid build (both grids in one launch via blockIdx.y)
// ---------------------------------------------------------------------------
__global__ void grid_hist2(const float* __restrict__ pos, const float* __restrict__ box) {
    int g = blockIdx.y;
    const float* p = g ? box : pos;
    int n = g ? NBOX : NQ;
    int i = blockIdx.x * blockDim.x + threadIdx.x;
    if (i >= n) return;
    int cx = cell_coord(p[3 * i + 0]);
    int cy = cell_coord(p[3 * i + 1]);
    int cz = cell_coord(p[3 * i + 2]);
    atomicAdd(&g_gcnt[g][(cz * GDIM + cy) * GDIM + cx], 1);
}

__global__ void grid_scan2() {
    int g = blockIdx.x;
    __shared__ int s[NCELLS];
    int t = threadIdx.x;
    int v = g_gcnt[g][t];
    s[t] = v;
    __syncthreads();
    for (int off = 1; off < NCELLS; off <<= 1) {
        int x = (t >= off) ? s[t - off] : 0;
        __syncthreads();
        s[t] += x;
        __syncthreads();
    }
    g_gstart[g][t + 1] = s[t];
    g_gcur[g][t] = s[t] - v;
    if (t == 0) g_gstart[g][0] = 0;
}

__global__ void grid_fill2(const float* __restrict__ pos, const float* __restrict__ box) {
    int g = blockIdx.y;
    const float* p = g ? box : pos;
    int n = g ? NBOX : NQ;
    int* list = g ? g_glistB : g_glistF;
    int i = blockIdx.x * blockDim.x + threadIdx.x;
    if (i >= n) return;
    int cx = cell_coord(p[3 * i + 0]);
    int cy = cell_coord(p[3 * i + 1]);
    int cz = cell_coord(p[3 * i + 2]);
    int slot = atomicAdd(&g_gcur[g][(cz * GDIM + cy) * GDIM + cx], 1);
    list[slot] = i;
}

// ---------------------------------------------------------------------------
// Neighbor search (both passes in one launch: y=0 fluid/self, y=1 box)
// ---------------------------------------------------------------------------
__global__ void nbr_grid2(const float* __restrict__ pos, const float* __restrict__ box) {
    int pass = blockIdx.y;
    const float* pin   = pass ? box : pos;
    const int*  glist  = pass ? g_glistB : g_glistF;
    const int*  gstart = g_gstart[pass];
    int selfExcl = pass ? 0 : 1;
    int* cnt_out  = pass ? g_ocnt  : g_fcnt;
    int* idx_out  = pass ? g_oidx  : g_fidx;
    int* cell_out = pass ? g_ocell : g_fcell;
    float* coef_out = pass ? g_ocoef : g_fcoef;

    int i = blockIdx.x;
    __shared__ float sd2[CAP];
    __shared__ int   sj[CAP];
    __shared__ int   ssel[KMAX];
    __shared__ int   scnt, skeep;
    int tid = threadIdx.x;
    if (tid == 0) { scnt = 0; skeep = 0; }
    __syncthreads();

    float qx = pos[3 * i + 0], qy = pos[3 * i + 1], qz = pos[3 * i + 2];
    const float R2 = RADIUS * RADIUS;

    int cx = cell_coord(qx), cy = cell_coord(qy), cz = cell_coord(qz);
    int x0 = max(cx - 1, 0), x1 = min(cx + 1, GDIM - 1);
    int y0 = max(cy - 1, 0), y1 = min(cy + 1, GDIM - 1);
    int z0 = max(cz - 1, 0), z1 = min(cz + 1, GDIM - 1);

    for (int z = z0; z <= z1; z++) {
        for (int y = y0; y <= y1; y++) {
            int cbase = (z * GDIM + y) * GDIM;
            int b = gstart[cbase + x0];
            int e = gstart[cbase + x1 + 1];
            for (int t = b + tid; t < e; t += blockDim.x) {
                int j = glist[t];
                if (selfExcl && j == i) continue;
                float dx = pin[3 * j + 0] - qx;
                float dy = pin[3 * j + 1] - qy;
                float dz = pin[3 * j + 2] - qz;
                float d2 = dx * dx + dy * dy + dz * dz;
                if (d2 <= R2) {
                    int p = atomicAdd(&scnt, 1);
                    if (p < CAP) { sd2[p] = d2; sj[p] = j; }
                }
            }
        }
    }
    __syncthreads();

    int cnt = min(scnt, CAP);
    int kcnt;
    if (cnt <= KMAX) {
        kcnt = cnt;
        for (int e = tid; e < cnt; e += blockDim.x) ssel[e] = sj[e];
    } else {
        kcnt = KMAX;
        for (int e = tid; e < cnt; e += blockDim.x) {
            float m2 = sd2[e]; int mj = sj[e]; int rank = 0;
            for (int q = 0; q < cnt; q++) {
                float o2 = sd2[q];
                rank += (o2 < m2) || (o2 == m2 && sj[q] < mj);
            }
            if (rank < KMAX) { int p = atomicAdd(&skeep, 1); ssel[p] = mj; }
        }
    }
    __syncthreads();
    if (tid == 0) cnt_out[i] = kcnt;

    const float EPS = 1e-12f;
    const float FP  = (float)(4.0 / 3.14159265358979323846);

    for (int k = tid; k < kcnt; k += blockDim.x) {
        int j = ssel[k];
        float rx = (pin[3 * j + 0] - qx) / RADIUS;
        float ry = (pin[3 * j + 1] - qy) / RADIUS;
        float rz = (pin[3 * j + 2] - qz) / RADIUS;

        float sq = rx * rx + ry * ry + rz * rz;
        float p1m = 1.0f - sq;
        float win = p1m * p1m * p1m;
        win = fminf(fmaxf(win, 0.f), 1.f);

        float nrm  = sqrtf(sq);
        float rxy2 = rx * rx + ry * ry;
        bool  polar = (1.25f * rz * rz) > rxy2;
        float s_pol = sqrtf(3.0f * nrm / (nrm + fabsf(rz) + EPS));
        float s_eq  = nrm / sqrtf(rxy2 + EPS);
        float xc = polar ? s_pol * rx : s_eq * rx;
        float yc = polar ? s_pol * ry : s_eq * ry;
        float zc = polar ? fsign(rz) * nrm : 1.5f * rz * s_eq;
        if (sq < 1e-12f) { xc = 0.f; yc = 0.f; zc = 0.f; }

        float rxy = sqrtf(xc * xc + yc * yc);
        float sx = (fabsf(xc) < EPS) ? EPS : xc;
        float sy = (fabsf(yc) < EPS) ? EPS : yc;
        float u1 = fsign(xc) * rxy;
        float v1 = u1 * FP * atanf(yc / sx);
        float v2 = fsign(yc) * rxy;
        float u2 = v2 * FP * atanf(xc / sy);
        float u, v;
        if (fabsf(xc) >= fabsf(yc)) { u = u1; v = v1; } else { u = u2; v = v2; }
        if (rxy < EPS) { u = 0.f; v = 0.f; }

        float gx = fminf(fmaxf((u  + 1.0f) * 0.5f * (float)(KS - 1), 0.f), (float)(KS - 1));
        float gy = fminf(fmaxf((v  + 1.0f) * 0.5f * (float)(KS - 1), 0.f), (float)(KS - 1));
        float gz = fminf(fmaxf((zc + 1.0f) * 0.5f * (float)(KS - 1), 0.f), (float)(KS - 1));
        int ix = min((int)floorf(gx), KS - 2);
        int iy = min((int)floorf(gy), KS - 2);
        int iz = min((int)floorf(gz), KS - 2);
        float tx = gx - (float)ix, ty = gy - (float)iy, tz = gz - (float)iz;

        int slot = i * KMAX + k;
        idx_out[slot]  = j;
        cell_out[slot] = (iz * KS + iy) * KS + ix;

        float wx[2] = {1.f - tx, tx};
        float wy[2] = {1.f - ty, ty};
        float wz[2] = {1.f - tz, tz};
        float* cf = coef_out + (size_t)slot * 8;
        #pragma unroll
        for (int dx = 0; dx < 2; dx++)
            #pragma unroll
            for (int dy = 0; dy < 2; dy++)
                #pragma unroll
                for (int dz = 0; dz < 2; dz++)
                    cf[dx * 4 + dy * 2 + dz] = wx[dx] * wy[dy] * wz[dz] * win;
    }
}

// ---------------------------------------------------------------------------
// Scatter with k-split (+ optional appended h columns for fused dense branch)
// Row layout: [ 64*F scatter | (EXTRA ? F : 0) appended relu(feats[i]) ]
// ---------------------------------------------------------------------------
template <int F, int SPLIT, int EXTRA>
__global__ void scatter_split(const int* __restrict__ cnt, const int* __restrict__ nidx,
                              const int* __restrict__ ncell, const float* __restrict__ ncoef,
                              const float* __restrict__ feats, int doRelu,
                              float* __restrict__ Sout, int ldS) {
    int i = blockIdx.x;
    extern __shared__ float shS[];            // SPLIT * 64 * F
    __shared__ float shC[KMAX * 8];
    __shared__ int   shI[KMAX];
    __shared__ int   shCe[KMAX];
    int tid = threadIdx.x;
    const int NT = F * SPLIT;
    const int nF = 64 * F;

    for (int q = tid; q < SPLIT * nF; q += NT) shS[q] = 0.f;
    int c = cnt[i];
    for (int q = tid; q < c; q += NT) {
        shI[q]  = nidx[i * KMAX + q];
        shCe[q] = ncell[i * KMAX + q];
    }
    for (int q = tid; q < c * 8; q += NT)
        shC[q] = ncoef[(size_t)i * KMAX * 8 + q];
    __syncthreads();

    {
        int f = tid % F;
        int s = tid / F;
        int k0 = (c * s) / SPLIT;
        int k1 = (c * (s + 1)) / SPLIT;
        float* my = shS + s * nF;
        const int OFF[8] = {0, 16, 4, 20, 1, 17, 5, 21};
        for (int k = k0; k < k1; k++) {
            int j = shI[k];
            float vv = feats[(size_t)j * F + f];
            if (doRelu) vv = fmaxf(vv, 0.f);
            int base = shCe[k] * F + f;
            #pragma unroll
            for (int cc = 0; cc < 8; cc++)
                my[base + OFF[cc] * F] += shC[k * 8 + cc] * vv;
        }
    }
    __syncthreads();

    float* dst = Sout + (size_t)i * ldS;
    for (int q = tid; q < nF; q += NT) {
        float v = shS[q];
        #pragma unroll
        for (int s = 1; s < SPLIT; s++) v += shS[s * nF + q];
        dst[q] = v;
    }
    if (EXTRA) {
        for (int f = tid; f < F; f += NT) {
            float v = feats[(size_t)i * F + f];
            if (doRelu) v = fmaxf(v, 0.f);
            dst[nF + f] = v;
        }
    }
}

// ---------------------------------------------------------------------------
// GEMM, N = 64, fp32 f32x2 FMA, split-K over blockIdx.y, two weight sources
// (rows < K1 from W1, rows >= K1 from W2).
// ---------------------------------------------------------------------------
__global__ void gemm64_k(const float* __restrict__ A, int lda, int M, int klen,
                         const float* __restrict__ W1, int K1, const float* __restrict__ W2,
                         float* __restrict__ outbase) {
    int bm = blockIdx.x * 64;
    int ks0 = blockIdx.y * klen;
    float* out = outbase + (size_t)blockIdx.y * M * 64;

    __shared__ float As[16][64];
    __shared__ float Bs[16][64];
    int tid = threadIdx.x;
    int ty = tid >> 4, tx = tid & 15;

    float2 acc[4][2];
    #pragma unroll
    for (int j = 0; j < 4; j++) { acc[j][0] = make_float2(0.f, 0.f); acc[j][1] = make_float2(0.f, 0.f); }

    int am = tid >> 2;
    int ak = (tid & 3) * 4;
    int bk = tid >> 4;
    int bn = (tid & 15) * 4;
    int arow = bm + am;

    for (int kt = ks0; kt < ks0 + klen; kt += 16) {
        float4 av = make_float4(0.f, 0.f, 0.f, 0.f);
        if (arow < M)
            av = *(const float4*)(A + (size_t)arow * lda + kt + ak);
        As[ak + 0][am] = av.x; As[ak + 1][am] = av.y;
        As[ak + 2][am] = av.z; As[ak + 3][am] = av.w;
        int krow = kt + bk;
        const float* wsrc = (krow < K1) ? (W1 + (size_t)krow * 64)
                                        : (W2 + (size_t)(krow - K1) * 64);
        *(float4*)&Bs[bk][bn] = *(const float4*)(wsrc + bn);
        __syncthreads();

        #pragma unroll
        for (int kk = 0; kk < 16; kk++) {
            float4 a = *(const float4*)&As[kk][ty * 4];
            float4 b = *(const float4*)&Bs[kk][tx * 4];
            float2 a01 = make_float2(a.x, a.y);
            float2 a23 = make_float2(a.z, a.w);
            acc[0][0] = ffma2(a01, make_float2(b.x, b.x), acc[0][0]);
            acc[0][1] = ffma2(a23, make_float2(b.x, b.x), acc[0][1]);
            acc[1][0] = ffma2(a01, make_float2(b.y, b.y), acc[1][0]);
            acc[1][1] = ffma2(a23, make_float2(b.y, b.y), acc[1][1]);
            acc[2][0] = ffma2(a01, make_float2(b.z, b.z), acc[2][0]);
            acc[2][1] = ffma2(a23, make_float2(b.z, b.z), acc[2][1]);
            acc[3][0] = ffma2(a01, make_float2(b.w, b.w), acc[3][0]);
            acc[3][1] = ffma2(a23, make_float2(b.w, b.w), acc[3][1]);
        }
        __syncthreads();
    }

    int r0 = bm + ty * 4;
    #pragma unroll
    for (int j = 0; j < 4; j++) {
        int col = tx * 4 + j;
        if (r0 + 0 < M) out[(size_t)(r0 + 0) * 64 + col] = acc[j][0].x;
        if (r0 + 1 < M) out[(size_t)(r0 + 1) * 64 + col] = acc[j][0].y;
        if (r0 + 2 < M) out[(size_t)(r0 + 2) * 64 + col] = acc[j][1].x;
        if (r0 + 3 < M) out[(size_t)(r0 + 3) * 64 + col] = acc[j][1].y;
    }
}

// ---------------------------------------------------------------------------
// combine: out = p0 + p1 + b1 + b2 (+ res)
// ---------------------------------------------------------------------------
__global__ void combine_kernel(const float* __restrict__ p0, const float* __restrict__ p1,
                               const float* __restrict__ b1, const float* __restrict__ b2,
                               const float* __restrict__ res, float* __restrict__ out, int M) {
    int idx = blockIdx.x * blockDim.x + threadIdx.x;
    if (idx >= M * 64) return;
    int c = idx & 63;
    float v = p0[idx] + p1[idx] + b1[c] + b2[c];
    if (res) v += res[idx];
    out[idx] = v;
}

// ---------------------------------------------------------------------------
// Small-O GEMM, W cached in shared, two weight sources + two biases.
// out = (A@[W1;W2] + bias1 + bias2) * scale
// ---------------------------------------------------------------------------
template <int O>
__global__ void gemm_small(const float* __restrict__ A, int lda, int M,
                           int K1, const float* __restrict__ W1,
                           int K2, const float* __restrict__ W2,
                           const float* __restrict__ bias1, const float* __restrict__ bias2,
                           float* __restrict__ out, int ldo, int ooff, float scale) {
    extern __shared__ float sW[];   // (K1+K2) * O
    int tid = threadIdx.x;
    int K = K1 + K2;
    for (int q = tid; q < K1 * O; q += blockDim.x) sW[q] = W1[q];
    for (int q = tid; q < K2 * O; q += blockDim.x) sW[K1 * O + q] = W2[q];
    __syncthreads();

    int warp = blockIdx.x * (blockDim.x >> 5) + (tid >> 5);
    int lane = tid & 31;
    if (warp >= M) return;
    const float* Ar = A + (size_t)warp * lda;

    float acc[O];
    #pragma unroll
    for (int o = 0; o < O; o++) acc[o] = 0.f;

    for (int k = lane; k < K; k += 32) {
        float a = Ar[k];
        const float* wr = sW + k * O;
        #pragma unroll
        for (int o = 0; o < O; o++) acc[o] += a * wr[o];
    }

    float myv = 0.f;
    #pragma unroll
    for (int o = 0; o < O; o++) {
        float v = acc[o];
        v += __shfl_xor_sync(0xffffffffu, v, 16);
        v += __shfl_xor_sync(0xffffffffu, v, 8);
        v += __shfl_xor_sync(0xffffffffu, v, 4);
        v += __shfl_xor_sync(0xffffffffu, v, 2);
        v += __shfl_xor_sync(0xffffffffu, v, 1);
        if (lane == o) myv = v;
    }
    if (lane < O) {
        float r = myv + (bias1 ? bias1[lane] : 0.f) + (bias2 ? bias2[lane] : 0.f);
        out[(size_t)warp * ldo + ooff + lane] = r * scale;
    }
}

// ---------------------------------------------------------------------------
// Host launch
// ---------------------------------------------------------------------------
template <typename T>
static T* symaddr(const void* sym) {
    void* p = nullptr;
    cudaGetSymbolAddress(&p, sym);
    return (T*)p;
}

extern "C" void kernel_launch(void* const* d_in, const int* in_sizes, int n_in,
                              void* d_out, int out_size) {
    cudaFuncSetAttribute(scatter_split<96, 2, 1>, cudaFuncAttributeMaxDynamicSharedMemorySize, 64 * 1024);
    cudaFuncSetAttribute(scatter_split<64, 3, 1>, cudaFuncAttributeMaxDynamicSharedMemorySize, 64 * 1024);
    cudaFuncSetAttribute(scatter_split<4, 32, 0>, cudaFuncAttributeMaxDynamicSharedMemorySize, 64 * 1024);
    cudaFuncSetAttribute(scatter_split<3, 32, 0>, cudaFuncAttributeMaxDynamicSharedMemorySize, 64 * 1024);
    cudaFuncSetAttribute(gemm_small<3>, cudaFuncAttributeMaxDynamicSharedMemorySize, 64 * 1024);
    cudaFuncSetAttribute(gemm_small<32>, cudaFuncAttributeMaxDynamicSharedMemorySize, 64 * 1024);

    const float* pos       = (const float*)d_in[0];
    const float* vel       = (const float*)d_in[1];
    const float* box       = (const float*)d_in[2];
    const float* box_feats = (const float*)d_in[3];
    const float* cf_w = (const float*)d_in[4];
    const float* cf_b = (const float*)d_in[5];
    const float* co_w = (const float*)d_in[6];
    const float* co_b = (const float*)d_in[7];
    const float* d0_w = (const float*)d_in[8];
    const float* d0_b = (const float*)d_in[9];
    const float* c1_w = (const float*)d_in[10];
    const float* c1_b = (const float*)d_in[11];
    const float* d1_w = (const float*)d_in[12];
    const float* d1_b = (const float*)d_in[13];
    const float* c2_w = (const float*)d_in[14];
    const float* c2_b = (const float*)d_in[15];
    const float* d2_w = (const float*)d_in[16];
    const float* d2_b = (const float*)d_in[17];
    const float* c3_w = (const float*)d_in[18];
    const float* c3_b = (const float*)d_in[19];
    const float* d3_w = (const float*)d_in[20];
    const float* d3_b = (const float*)d_in[21];
    float* out = (float*)d_out;

    float* S    = symaddr<float>(g_S);
    float* x96  = symaddr<float>(g_x96);
    float* ya   = symaddr<float>(g_ya);
    float* yb   = symaddr<float>(g_yb);
    float* part = symaddr<float>(g_part);
    float* ff   = symaddr<float>(g_ff);
    int*   fcnt  = symaddr<int>(g_fcnt);
    int*   fidx  = symaddr<int>(g_fidx);
    int*   fcell = symaddr<int>(g_fcell);
    float* fcoef = symaddr<float>(g_fcoef);
    int*   ocnt  = symaddr<int>(g_ocnt);
    int*   oidx  = symaddr<int>(g_oidx);
    int*   ocell = symaddr<int>(g_ocell);
    float* ocoef = symaddr<float>(g_ocoef);

    const int M = NQ;
    float* part0 = part;
    float* part1 = part + (size_t)M * 64;

    // 0) prep: ff, a_d0 into x96 cols 64..95, zero grid counters
    prep_kernel<<<(NQ + 255) / 256, 256>>>(vel, d0_w, d0_b);

    // 1) build hash grids
    dim3 gh((NQ + 255) / 256, 2);
    grid_hist2<<<gh, 256>>>(pos, box);
    grid_scan2<<<2, NCELLS>>>();
    grid_fill2<<<gh, 256>>>(pos, box);

    // 2) both neighbor searches in one launch
    dim3 gn(NQ, 2);
    nbr_grid2<<<gn, 128>>>(pos, box);

    // 3) first block: x96 = [a_co | a_cf | a_d0]
    scatter_split<4, 32, 0><<<NQ, 128, 32 * 64 * 4 * 4>>>(fcnt, fidx, fcell, fcoef, ff, 0, S, 256);
    gemm_small<32><<<(M + 7) / 8, 256, 256 * 32 * 4>>>(S, 256, M, 256, cf_w, 0, nullptr, cf_b, nullptr, x96, 96, 32, 1.f);
    scatter_split<3, 32, 0><<<NQ, 96, 32 * 64 * 3 * 4>>>(ocnt, oidx, ocell, ocoef, box_feats, 0, S, 192);
    gemm_small<32><<<(M + 7) / 8, 256, 192 * 32 * 4>>>(S, 192, M, 192, co_w, 0, nullptr, co_b, nullptr, x96, 96, 0, 1.f);

    dim3 g2((M + 63) / 64, 2);

    // 4) layer 1 (fused dense branch): ya = S1@[c1_w;d1_w] + c1_b + d1_b
    scatter_split<96, 2, 1><<<NQ, 192, 2 * 64 * 96 * 4>>>(fcnt, fidx, fcell, fcoef, x96, 1, S, 6240);
    gemm64_k<<<g2, 256>>>(S, 6240, M, 3120, c1_w, 6144, d1_w, part);
    combine_kernel<<<(M * 64 + 255) / 256, 256>>>(part0, part1, c1_b, d1_b, nullptr, ya, M);

    // 5) layer 2: yb = S2@[c2_w;d2_w] + c2_b + d2_b + ya
    scatter_split<64, 3, 1><<<NQ, 192, 3 * 64 * 64 * 4>>>(fcnt, fidx, fcell, fcoef, ya, 1, S, 4160);
    gemm64_k<<<g2, 256>>>(S, 4160, M, 2080, c2_w, 4096, d2_w, part);
    combine_kernel<<<(M * 64 + 255) / 256, 256>>>(part0, part1, c2_b, d2_b, ya, yb, M);

    // 6) layer 3 in a single GEMM: out = (S3@[c3_w;d3_w] + c3_b + d3_b) / 128
    scatter_split<64, 3, 1><<<NQ, 192, 3 * 64 * 64 * 4>>>(fcnt, fidx, fcell, fcoef, yb, 1, S, 4160);
    gemm_small<3><<<(M + 7) / 8, 256, 4160 * 3 * 4>>>(S, 4160, M, 4096, c3_w, 64, d3_w, c3_b, d3_b, out, 3, 0, 1.0f / 128.0f);
}

// round 7
// speedup vs baseline: 1.0376x; 1.0376x over previous
#include <cuda_runtime.h>
#include <cuda_bf16.h>
#include <cuda_fp16.h>
#include <math.h>

// ---------------------------------------------------------------------------
// Problem constants
// ---------------------------------------------------------------------------
#define NQ      6000
#define NBOX    3000
#define KMAX    80
#define CAP     256
#define KS      4
#define NCELL   64
#define RADIUS  0.1125f

#define GDIM    8
#define NCELLS  (GDIM*GDIM*GDIM)

// ---------------------------------------------------------------------------
// Device scratch (fp16 S halves the DRAM pipeline traffic)
// ---------------------------------------------------------------------------
__device__ __align__(16) __half g_S[(size_t)NQ * (64 * 96 + 96)];   // rows up to 6240 halves
__device__ __align__(16) float g_x96[NQ * 96];
__device__ __align__(16) float g_ya[NQ * 64];
__device__ __align__(16) float g_yb[NQ * 64];
__device__ __align__(16) float g_ff[NQ * 4];

__device__ int   g_fcnt[NQ];
__device__ int   g_fidx[NQ * KMAX];
__device__ int   g_fcell[NQ * KMAX];
__device__ __align__(16) float g_fcoef[(size_t)NQ * KMAX * 8];

__device__ int   g_ocnt[NQ];
__device__ int   g_oidx[NQ * KMAX];
__device__ int   g_ocell[NQ * KMAX];
__device__ __align__(16) float g_ocoef[(size_t)NQ * KMAX * 8];

// hash grids (0 = fluid/pos, 1 = box). NOTE: g_gcnt starts zeroed (static init)
// and is re-zeroed by grid_scan2 after it reads it -> every replay sees zeros.
__device__ int g_gcnt[2][NCELLS];
__device__ int g_gstart[2][NCELLS + 1];
__device__ int g_gcur[2][NCELLS];
__device__ int g_glistF[NQ];
__device__ int g_glistB[NBOX];

// ---------------------------------------------------------------------------
// Helpers
// ---------------------------------------------------------------------------
__device__ __forceinline__ float2 ffma2(float2 a, float2 b, float2 c) {
    float2 d;
    asm("{\n\t"
        ".reg .b64 ra, rb, rc;\n\t"
        "mov.b64 ra, {%2, %3};\n\t"
        "mov.b64 rb, {%4, %5};\n\t"
        "mov.b64 rc, {%6, %7};\n\t"
        "fma.rn.f32x2 rc, ra, rb, rc;\n\t"
        "mov.b64 {%0, %1}, rc;\n\t"
        "}"
        : "=f"(d.x), "=f"(d.y)
        : "f"(a.x), "f"(a.y), "f"(b.x), "f"(b.y), "f"(c.x), "f"(c.y));
    return d;
}

__device__ __forceinline__ float fsign(float x) {
    return (x > 0.f) ? 1.f : ((x < 0.f) ? -1.f : 0.f);
}

__device__ __forceinline__ int cell_coord(float x) {
    int c = (int)(x * (float)GDIM);
    return min(max(c, 0), GDIM - 1);
}

// ---------------------------------------------------------------------------
// Hash grid build
// ---------------------------------------------------------------------------
__global__ void grid_hist2(const float* __restrict__ pos, const float* __restrict__ box) {
    int g = blockIdx.y;
    const float* p = g ? box : pos;
    int n = g ? NBOX : NQ;
    int i = blockIdx.x * blockDim.x + threadIdx.x;
    if (i >= n) return;
    int cx = cell_coord(p[3 * i + 0]);
    int cy = cell_coord(p[3 * i + 1]);
    int cz = cell_coord(p[3 * i + 2]);
    atomicAdd(&g_gcnt[g][(cz * GDIM + cy) * GDIM + cx], 1);
}

__global__ void grid_scan2() {
    int g = blockIdx.x;
    __shared__ int s[NCELLS];
    int t = threadIdx.x;
    int v = g_gcnt[g][t];
    g_gcnt[g][t] = 0;          // reset for next replay (deterministic)
    s[t] = v;
    __syncthreads();
    for (int off = 1; off < NCELLS; off <<= 1) {
        int x = (t >= off) ? s[t - off] : 0;
        __syncthreads();
        s[t] += x;
        __syncthreads();
    }
    g_gstart[g][t + 1] = s[t];
    g_gcur[g][t] = s[t] - v;
    if (t == 0) g_gstart[g][0] = 0;
}

__global__ void grid_fill2(const float* __restrict__ pos, const float* __restrict__ box) {
    int g = blockIdx.y;
    const float* p = g ? box : pos;
    int n = g ? NBOX : NQ;
    int* list = g ? g_glistB : g_glistF;
    int i = blockIdx.x * blockDim.x + threadIdx.x;
    if (i >= n) return;
    int cx = cell_coord(p[3 * i + 0]);
    int cy = cell_coord(p[3 * i + 1]);
    int cz = cell_coord(p[3 * i + 2]);
    int slot = atomicAdd(&g_gcur[g][(cz * GDIM + cy) * GDIM + cx], 1);
    list[slot] = i;
}

// ---------------------------------------------------------------------------
// Neighbor search (both passes in one launch)
// ---------------------------------------------------------------------------
__global__ void nbr_grid2(const float* __restrict__ pos, const float* __restrict__ box) {
    int pass = blockIdx.y;
    const float* pin   = pass ? box : pos;
    const int*  glist  = pass ? g_glistB : g_glistF;
    const int*  gstart = g_gstart[pass];
    int selfExcl = pass ? 0 : 1;
    int* cnt_out  = pass ? g_ocnt  : g_fcnt;
    int* idx_out  = pass ? g_oidx  : g_fidx;
    int* cell_out = pass ? g_ocell : g_fcell;
    float* coef_out = pass ? g_ocoef : g_fcoef;

    int i = blockIdx.x;
    __shared__ float sd2[CAP];
    __shared__ int   sj[CAP];
    __shared__ int   ssel[KMAX];
    __shared__ int   scnt, skeep;
    int tid = threadIdx.x;
    if (tid == 0) { scnt = 0; skeep = 0; }
    __syncthreads();

    float qx = pos[3 * i + 0], qy = pos[3 * i + 1], qz = pos[3 * i + 2];
    const float R2 = RADIUS * RADIUS;

    int cx = cell_coord(qx), cy = cell_coord(qy), cz = cell_coord(qz);
    int x0 = max(cx - 1, 0), x1 = min(cx + 1, GDIM - 1);
    int y0 = max(cy - 1, 0), y1 = min(cy + 1, GDIM - 1);
    int z0 = max(cz - 1, 0), z1 = min(cz + 1, GDIM - 1);

    for (int z = z0; z <= z1; z++) {
        for (int y = y0; y <= y1; y++) {
            int cbase = (z * GDIM + y) * GDIM;
            int b = gstart[cbase + x0];
            int e = gstart[cbase + x1 + 1];
            for (int t = b + tid; t < e; t += blockDim.x) {
                int j = glist[t];
                if (selfExcl && j == i) continue;
                float dx = pin[3 * j + 0] - qx;
                float dy = pin[3 * j + 1] - qy;
                float dz = pin[3 * j + 2] - qz;
                float d2 = dx * dx + dy * dy + dz * dz;
                if (d2 <= R2) {
                    int p = atomicAdd(&scnt, 1);
                    if (p < CAP) { sd2[p] = d2; sj[p] = j; }
                }
            }
        }
    }
    __syncthreads();

    int cnt = min(scnt, CAP);
    int kcnt;
    if (cnt <= KMAX) {
        kcnt = cnt;
        for (int e = tid; e < cnt; e += blockDim.x) ssel[e] = sj[e];
    } else {
        kcnt = KMAX;
        for (int e = tid; e < cnt; e += blockDim.x) {
            float m2 = sd2[e]; int mj = sj[e]; int rank = 0;
            for (int q = 0; q < cnt; q++) {
                float o2 = sd2[q];
                rank += (o2 < m2) || (o2 == m2 && sj[q] < mj);
            }
            if (rank < KMAX) { int p = atomicAdd(&skeep, 1); ssel[p] = mj; }
        }
    }
    __syncthreads();
    if (tid == 0) cnt_out[i] = kcnt;

    const float EPS = 1e-12f;
    const float FP  = (float)(4.0 / 3.14159265358979323846);

    for (int k = tid; k < kcnt; k += blockDim.x) {
        int j = ssel[k];
        float rx = (pin[3 * j + 0] - qx) / RADIUS;
        float ry = (pin[3 * j + 1] - qy) / RADIUS;
        float rz = (pin[3 * j + 2] - qz) / RADIUS;

        float sq = rx * rx + ry * ry + rz * rz;
        float p1m = 1.0f - sq;
        float win = p1m * p1m * p1m;
        win = fminf(fmaxf(win, 0.f), 1.f);

        float nrm  = sqrtf(sq);
        float rxy2 = rx * rx + ry * ry;
        bool  polar = (1.25f * rz * rz) > rxy2;
        float s_pol = sqrtf(3.0f * nrm / (nrm + fabsf(rz) + EPS));
        float s_eq  = nrm / sqrtf(rxy2 + EPS);
        float xc = polar ? s_pol * rx : s_eq * rx;
        float yc = polar ? s_pol * ry : s_eq * ry;
        float zc = polar ? fsign(rz) * nrm : 1.5f * rz * s_eq;
        if (sq < 1e-12f) { xc = 0.f; yc = 0.f; zc = 0.f; }

        float rxy = sqrtf(xc * xc + yc * yc);
        float sx = (fabsf(xc) < EPS) ? EPS : xc;
        float sy = (fabsf(yc) < EPS) ? EPS : yc;
        float u1 = fsign(xc) * rxy;
        float v1 = u1 * FP * atanf(yc / sx);
        float v2 = fsign(yc) * rxy;
        float u2 = v2 * FP * atanf(xc / sy);
        float u, v;
        if (fabsf(xc) >= fabsf(yc)) { u = u1; v = v1; } else { u = u2; v = v2; }
        if (rxy < EPS) { u = 0.f; v = 0.f; }

        float gx = fminf(fmaxf((u  + 1.0f) * 0.5f * (float)(KS - 1), 0.f), (float)(KS - 1));
        float gy = fminf(fmaxf((v  + 1.0f) * 0.5f * (float)(KS - 1), 0.f), (float)(KS - 1));
        float gz = fminf(fmaxf((zc + 1.0f) * 0.5f * (float)(KS - 1), 0.f), (float)(KS - 1));
        int ix = min((int)floorf(gx), KS - 2);
        int iy = min((int)floorf(gy), KS - 2);
        int iz = min((int)floorf(gz), KS - 2);
        float tx = gx - (float)ix, ty = gy - (float)iy, tz = gz - (float)iz;

        int slot = i * KMAX + k;
        idx_out[slot]  = j;
        cell_out[slot] = (iz * KS + iy) * KS + ix;

        float wx[2] = {1.f - tx, tx};
        float wy[2] = {1.f - ty, ty};
        float wz[2] = {1.f - tz, tz};
        float* cf = coef_out + (size_t)slot * 8;
        #pragma unroll
        for (int dx = 0; dx < 2; dx++)
            #pragma unroll
            for (int dy = 0; dy < 2; dy++)
                #pragma unroll
                for (int dz = 0; dz < 2; dz++)
                    cf[dx * 4 + dy * 2 + dz] = wx[dx] * wy[dy] * wz[dz] * win;
    }
}

// ---------------------------------------------------------------------------
// prep: ff = [1,vel]; x96[:,64:96] = ff @ d0_w + d0_b
// ---------------------------------------------------------------------------
__global__ void prep_kernel(const float* __restrict__ vel,
                            const float* __restrict__ d0_w, const float* __restrict__ d0_b) {
    int i = blockIdx.x * blockDim.x + threadIdx.x;
    if (i >= NQ) return;
    float f1 = vel[i * 3 + 0], f2 = vel[i * 3 + 1], f3 = vel[i * 3 + 2];
    g_ff[i * 4 + 0] = 1.0f;
    g_ff[i * 4 + 1] = f1;
    g_ff[i * 4 + 2] = f2;
    g_ff[i * 4 + 3] = f3;
    #pragma unroll 8
    for (int o = 0; o < 32; o++) {
        g_x96[i * 96 + 64 + o] = d0_w[o] + f1 * d0_w[32 + o] + f2 * d0_w[64 + o]
                                 + f3 * d0_w[96 + o] + d0_b[o];
    }
}

// ---------------------------------------------------------------------------
// Scatter with k-split, fp32 smem accumulation, fp16 writeout.
// Row layout: [ 64*F scatter | (EXTRA ? F : 0) appended relu(feats[i]) ]
// ---------------------------------------------------------------------------
template <int F, int SPLIT, int EXTRA>
__global__ void scatter_split(const int* __restrict__ cnt, const int* __restrict__ nidx,
                              const int* __restrict__ ncell, const float* __restrict__ ncoef,
                              const float* __restrict__ feats, int doRelu,
                              __half* __restrict__ Sout, int ldS) {
    int i = blockIdx.x;
    extern __shared__ float shS[];            // SPLIT * 64 * F
    __shared__ float shC[KMAX * 8];
    __shared__ int   shI[KMAX];
    __shared__ int   shCe[KMAX];
    int tid = threadIdx.x;
    const int NT = F * SPLIT;
    const int nF = 64 * F;

    for (int q = tid; q < SPLIT * nF; q += NT) shS[q] = 0.f;
    int c = cnt[i];
    for (int q = tid; q < c; q += NT) {
        shI[q]  = nidx[i * KMAX + q];
        shCe[q] = ncell[i * KMAX + q];
    }
    for (int q = tid; q < c * 8; q += NT)
        shC[q] = ncoef[(size_t)i * KMAX * 8 + q];
    __syncthreads();

    {
        int f = tid % F;
        int s = tid / F;
        int k0 = (c * s) / SPLIT;
        int k1 = (c * (s + 1)) / SPLIT;
        float* my = shS + s * nF;
        const int OFF[8] = {0, 16, 4, 20, 1, 17, 5, 21};
        for (int k = k0; k < k1; k++) {
            int j = shI[k];
            float vv = feats[(size_t)j * F + f];
            if (doRelu) vv = fmaxf(vv, 0.f);
            int base = shCe[k] * F + f;
            #pragma unroll
            for (int cc = 0; cc < 8; cc++)
                my[base + OFF[cc] * F] += shC[k * 8 + cc] * vv;
        }
    }
    __syncthreads();

    __half* dst = Sout + (size_t)i * ldS;
    for (int q = tid * 2; q < nF; q += NT * 2) {
        float v0 = shS[q], v1 = shS[q + 1];
        #pragma unroll
        for (int s = 1; s < SPLIT; s++) { v0 += shS[s * nF + q]; v1 += shS[s * nF + q + 1]; }
        *(__half2*)(dst + q) = __floats2half2_rn(v0, v1);
    }
    if (EXTRA) {
        for (int f = tid; f < F; f += NT) {
            float v = feats[(size_t)i * F + f];
            if (doRelu) v = fmaxf(v, 0.f);
            dst[nF + f] = __float2half_rn(v);
        }
    }
}

// ---------------------------------------------------------------------------
// GEMM, fp16 A, N=64, M32-tile, full-K, fused epilogue:
// out = A @ [W1; W2] + b1 + b2 (+ res)
// ---------------------------------------------------------------------------
__global__ void gemm64h(const __half* __restrict__ A, int lda, int M, int K,
                        const float* __restrict__ W1, int K1, const float* __restrict__ W2,
                        const float* __restrict__ b1, const float* __restrict__ b2,
                        const float* __restrict__ res, float* __restrict__ out) {
    int bm = blockIdx.x * 32;
    __shared__ __half As[32][32];
    __shared__ float  Ws[32][64];
    int tid = threadIdx.x;
    int arow = tid >> 3, aseg = tid & 7;      // A-tile loads: 32 rows x 4 halves each seg
    int ty = tid >> 4, tx = tid & 15;         // compute map: rows ty*2,ty*2+1; cols tx*4..+3
    int r0 = ty * 2, r1 = r0 + 1;

    float2 acc[4];
    #pragma unroll
    for (int j = 0; j < 4; j++) acc[j] = make_float2(0.f, 0.f);

    int garow = bm + arow;
    bool aok = garow < M;
    const __half* Abase = A + (size_t)garow * lda;

    for (int kt = 0; kt < K; kt += 32) {
        uint2 av = make_uint2(0u, 0u);
        if (aok) av = *(const uint2*)(Abase + kt + aseg * 4);
        *(uint2*)&As[arow][aseg * 4] = av;

        int krow = kt + arow;
        const float* wsrc = (krow < K1) ? (W1 + (size_t)krow * 64)
                                        : (W2 + (size_t)(krow - K1) * 64);
        *(float4*)&Ws[arow][aseg * 8]     = *(const float4*)(wsrc + aseg * 8);
        *(float4*)&Ws[arow][aseg * 8 + 4] = *(const float4*)(wsrc + aseg * 8 + 4);
        __syncthreads();

        #pragma unroll
        for (int kk = 0; kk < 32; kk += 2) {
            float2 a0 = __half22float2(*(const __half2*)&As[r0][kk]);
            float2 a1 = __half22float2(*(const __half2*)&As[r1][kk]);
            float4 w0 = *(const float4*)&Ws[kk][tx * 4];
            float4 w1 = *(const float4*)&Ws[kk + 1][tx * 4];
            float2 p0 = make_float2(a0.x, a1.x);   // k = kk
            float2 p1 = make_float2(a0.y, a1.y);   // k = kk+1
            acc[0] = ffma2(p0, make_float2(w0.x, w0.x), acc[0]);
            acc[1] = ffma2(p0, make_float2(w0.y, w0.y), acc[1]);
            acc[2] = ffma2(p0, make_float2(w0.z, w0.z), acc[2]);
            acc[3] = ffma2(p0, make_float2(w0.w, w0.w), acc[3]);
            acc[0] = ffma2(p1, make_float2(w1.x, w1.x), acc[0]);
            acc[1] = ffma2(p1, make_float2(w1.y, w1.y), acc[1]);
            acc[2] = ffma2(p1, make_float2(w1.z, w1.z), acc[2]);
            acc[3] = ffma2(p1, make_float2(w1.w, w1.w), acc[3]);
        }
        __syncthreads();
    }

    int gr0 = bm + r0, gr1 = bm + r1;
    #pragma unroll
    for (int j = 0; j < 4; j++) {
        int col = tx * 4 + j;
        float bb = b1[col] + b2[col];
        if (gr0 < M) {
            float v = acc[j].x + bb;
            if (res) v += res[(size_t)gr0 * 64 + col];
            out[(size_t)gr0 * 64 + col] = v;
        }
        if (gr1 < M) {
            float v = acc[j].y + bb;
            if (res) v += res[(size_t)gr1 * 64 + col];
            out[(size_t)gr1 * 64 + col] = v;
        }
    }
}

// ---------------------------------------------------------------------------
// Small-O GEMM, fp16 A, transposed padded W cache [O][K+1] (conflict-free).
// out = (A @ [W1;W2] + bias1 + bias2) * scale
// ---------------------------------------------------------------------------
template <int O>
__global__ void gemm_small(const __half* __restrict__ A, int lda, int M,
                           int K1, const float* __restrict__ W1,
                           int K2, const float* __restrict__ W2,
                           const float* __restrict__ bias1, const float* __restrict__ bias2,
                           float* __restrict__ out, int ldo, int ooff, float scale) {
    extern __shared__ float sW[];   // O * (K+1), transposed
    int tid = threadIdx.x;
    int K = K1 + K2;
    int KP = K + 1;
    for (int q = tid; q < K1 * O; q += blockDim.x) {
        int k = q / O, o = q - k * O;
        sW[o * KP + k] = W1[q];
    }
    for (int q = tid; q < K2 * O; q += blockDim.x) {
        int k = q / O, o = q - k * O;
        sW[o * KP + K1 + k] = W2[q];
    }
    __syncthreads();

    int warp = blockIdx.x * (blockDim.x >> 5) + (tid >> 5);
    int lane = tid & 31;
    if (warp >= M) return;
    const __half* Ar = A + (size_t)warp * lda;

    float acc[O];
    #pragma unroll
    for (int o = 0; o < O; o++) acc[o] = 0.f;

    for (int k = lane * 2; k < K; k += 64) {
        float2 a = __half22float2(*(const __half2*)(Ar + k));
        #pragma unroll
        for (int o = 0; o < O; o++)
            acc[o] += a.x * sW[o * KP + k] + a.y * sW[o * KP + k + 1];
    }

    float myv = 0.f;
    #pragma unroll
    for (int o = 0; o < O; o++) {
        float v = acc[o];
        v += __shfl_xor_sync(0xffffffffu, v, 16);
        v += __shfl_xor_sync(0xffffffffu, v, 8);
        v += __shfl_xor_sync(0xffffffffu, v, 4);
        v += __shfl_xor_sync(0xffffffffu, v, 2);
        v += __shfl_xor_sync(0xffffffffu, v, 1);
        if (lane == o) myv = v;
    }
    if (lane < O) {
        float r = myv + (bias1 ? bias1[lane] : 0.f) + (bias2 ? bias2[lane] : 0.f);
        out[(size_t)warp * ldo + ooff + lane] = r * scale;
    }
}

// ---------------------------------------------------------------------------
// Host launch
// ---------------------------------------------------------------------------
template <typename T>
static T* symaddr(const void* sym) {
    void* p = nullptr;
    cudaGetSymbolAddress(&p, sym);
    return (T*)p;
}

extern "C" void kernel_launch(void* const* d_in, const int* in_sizes, int n_in,
                              void* d_out, int out_size) {
    cudaFuncSetAttribute(scatter_split<96, 2, 1>, cudaFuncAttributeMaxDynamicSharedMemorySize, 64 * 1024);
    cudaFuncSetAttribute(scatter_split<64, 3, 1>, cudaFuncAttributeMaxDynamicSharedMemorySize, 64 * 1024);
    cudaFuncSetAttribute(scatter_split<4, 32, 0>, cudaFuncAttributeMaxDynamicSharedMemorySize, 64 * 1024);
    cudaFuncSetAttribute(scatter_split<3, 32, 0>, cudaFuncAttributeMaxDynamicSharedMemorySize, 64 * 1024);
    cudaFuncSetAttribute(gemm_small<3>, cudaFuncAttributeMaxDynamicSharedMemorySize, 64 * 1024);
    cudaFuncSetAttribute(gemm_small<32>, cudaFuncAttributeMaxDynamicSharedMemorySize, 64 * 1024);

    const float* pos       = (const float*)d_in[0];
    const float* vel       = (const float*)d_in[1];
    const float* box       = (const float*)d_in[2];
    const float* box_feats = (const float*)d_in[3];
    const float* cf_w = (const float*)d_in[4];
    const float* cf_b = (const float*)d_in[5];
    const float* co_w = (const float*)d_in[6];
    const float* co_b = (const float*)d_in[7];
    const float* d0_w = (const float*)d_in[8];
    const float* d0_b = (const float*)d_in[9];
    const float* c1_w = (const float*)d_in[10];
    const float* c1_b = (const float*)d_in[11];
    const float* d1_w = (const float*)d_in[12];
    const float* d1_b = (const float*)d_in[13];
    const float* c2_w = (const float*)d_in[14];
    const float* c2_b = (const float*)d_in[15];
    const float* d2_w = (const float*)d_in[16];
    const float* d2_b = (const float*)d_in[17];
    const float* c3_w = (const float*)d_in[18];
    const float* c3_b = (const float*)d_in[19];
    const float* d3_w = (const float*)d_in[20];
    const float* d3_b = (const float*)d_in[21];
    float* out = (float*)d_out;

    __half* S   = symaddr<__half>(g_S);
    float* x96  = symaddr<float>(g_x96);
    float* ya   = symaddr<float>(g_ya);
    float* yb   = symaddr<float>(g_yb);
    float* ff   = symaddr<float>(g_ff);
    int*   fcnt  = symaddr<int>(g_fcnt);
    int*   fidx  = symaddr<int>(g_fidx);
    int*   fcell = symaddr<int>(g_fcell);
    float* fcoef = symaddr<float>(g_fcoef);
    int*   ocnt  = symaddr<int>(g_ocnt);
    int*   oidx  = symaddr<int>(g_oidx);
    int*   ocell = symaddr<int>(g_ocell);
    float* ocoef = symaddr<float>(g_ocoef);

    const int M = NQ;

    // 0-2) hash grids (counters pre-zeroed; scan re-zeroes them for next replay)
    dim3 gh((NQ + 255) / 256, 2);
    grid_hist2<<<gh, 256>>>(pos, box);                          // idx 0
    grid_scan2<<<2, NCELLS>>>();                                // idx 1
    grid_fill2<<<gh, 256>>>(pos, box);                          // idx 2

    // 3) neighbor search (lands on ncu's profiled slot)
    dim3 gn(NQ, 2);
    nbr_grid2<<<gn, 128>>>(pos, box);                           // idx 3

    // 4) prep (independent of nbr)
    prep_kernel<<<(NQ + 255) / 256, 256>>>(vel, d0_w, d0_b);    // idx 4

    // 5) first block: x96 = [a_co | a_cf | a_d0]
    scatter_split<4, 32, 0><<<NQ, 128, 32 * 64 * 4 * 4>>>(fcnt, fidx, fcell, fcoef, ff, 0, S, 256);
    gemm_small<32><<<(M + 7) / 8, 256, 257 * 32 * 4>>>(S, 256, M, 256, cf_w, 0, nullptr, cf_b, nullptr, x96, 96, 32, 1.f);
    scatter_split<3, 32, 0><<<NQ, 96, 32 * 64 * 3 * 4>>>(ocnt, oidx, ocell, ocoef, box_feats, 0, S, 192);
    gemm_small<32><<<(M + 7) / 8, 256, 193 * 32 * 4>>>(S, 192, M, 192, co_w, 0, nullptr, co_b, nullptr, x96, 96, 0, 1.f);

    dim3 gg((M + 31) / 32);

    // 6) layer 1: ya = S1 @ [c1_w; d1_w] + c1_b + d1_b
    scatter_split<96, 2, 1><<<NQ, 192, 2 * 64 * 96 * 4>>>(fcnt, fidx, fcell, fcoef, x96, 1, S, 6240);
    gemm64h<<<gg, 256>>>(S, 6240, M, 6240, c1_w, 6144, d1_w, c1_b, d1_b, nullptr, ya);

    // 7) layer 2: yb = S2 @ [c2_w; d2_w] + c2_b + d2_b + ya
    scatter_split<64, 3, 1><<<NQ, 192, 3 * 64 * 64 * 4>>>(fcnt, fidx, fcell, fcoef, ya, 1, S, 4160);
    gemm64h<<<gg, 256>>>(S, 4160, M, 4160, c2_w, 4096, d2_w, c2_b, d2_b, ya, yb);

    // 8) layer 3: out = (S3 @ [c3_w; d3_w] + c3_b + d3_b) / 128
    scatter_split<64, 3, 1><<<NQ, 192, 3 * 64 * 64 * 4>>>(fcnt, fidx, fcell, fcoef, yb, 1, S, 4160);
    gemm_small<3><<<(M + 7) / 8, 256, 4161 * 3 * 4>>>(S, 4160, M, 4096, c3_w, 64, d3_w, c3_b, d3_b, out, 3, 0, 1.0f / 128.0f);
}

// round 9
// speedup vs baseline: 1.4977x; 1.4434x over previous
#include <cuda_runtime.h>
#include <cuda_bf16.h>
#include <cuda_fp16.h>
#include <math.h>

// ---------------------------------------------------------------------------
// Problem constants
// ---------------------------------------------------------------------------
#define NQ      6000
#define NBOX    3000
#define KMAX    80
#define CAP     256
#define KS      4
#define NCELL   64
#define RADIUS  0.1125f

#define GDIM    8
#define NCELLS  (GDIM*GDIM*GDIM)

#define K1TOT   6240     // layer1 GEMM K (6144 conv + 96 dense)
#define K2TOT   4160     // layer2 GEMM K (4096 conv + 64 dense)

// ---------------------------------------------------------------------------
// Device scratch
// ---------------------------------------------------------------------------
__device__ __align__(16) __half g_S[(size_t)NQ * K1TOT];
__device__ __align__(16) float g_x96[NQ * 96];
__device__ __align__(16) float g_ya[NQ * 64];
__device__ __align__(16) float g_yb[NQ * 64];
__device__ __align__(16) float g_ff[NQ * 4];
__device__ __align__(16) __half g_Wt1[64 * K1TOT];   // [n][k] fp16, layer1
__device__ __align__(16) __half g_Wt2[64 * K2TOT];   // [n][k] fp16, layer2

__device__ int   g_fcnt[NQ];
__device__ int   g_fidx[NQ * KMAX];
__device__ int   g_fcell[NQ * KMAX];
__device__ __align__(16) float g_fcoef[(size_t)NQ * KMAX * 8];

__device__ int   g_ocnt[NQ];
__device__ int   g_oidx[NQ * KMAX];
__device__ int   g_ocell[NQ * KMAX];
__device__ __align__(16) float g_ocoef[(size_t)NQ * KMAX * 8];

// hash grids (0 = fluid/pos, 1 = box); counters self-re-zeroed in grid_scan2
__device__ int g_gcnt[2][NCELLS];
__device__ int g_gstart[2][NCELLS + 1];
__device__ int g_gcur[2][NCELLS];
__device__ int g_glistF[NQ];
__device__ int g_glistB[NBOX];

// ---------------------------------------------------------------------------
// Helpers
// ---------------------------------------------------------------------------
__device__ __forceinline__ float fsign(float x) {
    return (x > 0.f) ? 1.f : ((x < 0.f) ? -1.f : 0.f);
}

__device__ __forceinline__ int cell_coord(float x) {
    int c = (int)(x * (float)GDIM);
    return min(max(c, 0), GDIM - 1);
}

__device__ __forceinline__ void mma16816(float4& d, unsigned a0, unsigned a1,
                                         unsigned a2, unsigned a3,
                                         unsigned b0, unsigned b1) {
    asm volatile(
        "mma.sync.aligned.m16n8k16.row.col.f32.f16.f16.f32 "
        "{%0,%1,%2,%3}, {%4,%5,%6,%7}, {%8,%9}, {%0,%1,%2,%3};"
        : "+f"(d.x), "+f"(d.y), "+f"(d.z), "+f"(d.w)
        : "r"(a0), "r"(a1), "r"(a2), "r"(a3), "r"(b0), "r"(b1));
}

// ---------------------------------------------------------------------------
// Hash grid build
// ---------------------------------------------------------------------------
__global__ void grid_hist2(const float* __restrict__ pos, const float* __restrict__ box) {
    int g = blockIdx.y;
    const float* p = g ? box : pos;
    int n = g ? NBOX : NQ;
    int i = blockIdx.x * blockDim.x + threadIdx.x;
    if (i >= n) return;
    int cx = cell_coord(p[3 * i + 0]);
    int cy = cell_coord(p[3 * i + 1]);
    int cz = cell_coord(p[3 * i + 2]);
    atomicAdd(&g_gcnt[g][(cz * GDIM + cy) * GDIM + cx], 1);
}

__global__ void grid_scan2() {
    int g = blockIdx.x;
    __shared__ int s[NCELLS];
    int t = threadIdx.x;
    int v = g_gcnt[g][t];
    g_gcnt[g][t] = 0;          // reset for next replay (deterministic)
    s[t] = v;
    __syncthreads();
    for (int off = 1; off < NCELLS; off <<= 1) {
        int x = (t >= off) ? s[t - off] : 0;
        __syncthreads();
        s[t] += x;
        __syncthreads();
    }
    g_gstart[g][t + 1] = s[t];
    g_gcur[g][t] = s[t] - v;
    if (t == 0) g_gstart[g][0] = 0;
}

__global__ void grid_fill2(const float* __restrict__ pos, const float* __restrict__ box) {
    int g = blockIdx.y;
    const float* p = g ? box : pos;
    int n = g ? NBOX : NQ;
    int* list = g ? g_glistB : g_glistF;
    int i = blockIdx.x * blockDim.x + threadIdx.x;
    if (i >= n) return;
    int cx = cell_coord(p[3 * i + 0]);
    int cy = cell_coord(p[3 * i + 1]);
    int cz = cell_coord(p[3 * i + 2]);
    int slot = atomicAdd(&g_gcur[g][(cz * GDIM + cy) * GDIM + cx], 1);
    list[slot] = i;
}

// ---------------------------------------------------------------------------
// Neighbor search (both passes in one launch)
// ---------------------------------------------------------------------------
__global__ void nbr_grid2(const float* __restrict__ pos, const float* __restrict__ box) {
    int pass = blockIdx.y;
    const float* pin   = pass ? box : pos;
    const int*  glist  = pass ? g_glistB : g_glistF;
    const int*  gstart = g_gstart[pass];
    int selfExcl = pass ? 0 : 1;
    int* cnt_out  = pass ? g_ocnt  : g_fcnt;
    int* idx_out  = pass ? g_oidx  : g_fidx;
    int* cell_out = pass ? g_ocell : g_fcell;
    float* coef_out = pass ? g_ocoef : g_fcoef;

    int i = blockIdx.x;
    __shared__ float sd2[CAP];
    __shared__ int   sj[CAP];
    __shared__ int   ssel[KMAX];
    __shared__ int   scnt, skeep;
    int tid = threadIdx.x;
    if (tid == 0) { scnt = 0; skeep = 0; }
    __syncthreads();

    float qx = pos[3 * i + 0], qy = pos[3 * i + 1], qz = pos[3 * i + 2];
    const float R2 = RADIUS * RADIUS;

    int cx = cell_coord(qx), cy = cell_coord(qy), cz = cell_coord(qz);
    int x0 = max(cx - 1, 0), x1 = min(cx + 1, GDIM - 1);
    int y0 = max(cy - 1, 0), y1 = min(cy + 1, GDIM - 1);
    int z0 = max(cz - 1, 0), z1 = min(cz + 1, GDIM - 1);

    for (int z = z0; z <= z1; z++) {
        for (int y = y0; y <= y1; y++) {
            int cbase = (z * GDIM + y) * GDIM;
            int b = gstart[cbase + x0];
            int e = gstart[cbase + x1 + 1];
            for (int t = b + tid; t < e; t += blockDim.x) {
                int j = glist[t];
                if (selfExcl && j == i) continue;
                float dx = pin[3 * j + 0] - qx;
                float dy = pin[3 * j + 1] - qy;
                float dz = pin[3 * j + 2] - qz;
                float d2 = dx * dx + dy * dy + dz * dz;
                if (d2 <= R2) {
                    int p = atomicAdd(&scnt, 1);
                    if (p < CAP) { sd2[p] = d2; sj[p] = j; }
                }
            }
        }
    }
    __syncthreads();

    int cnt = min(scnt, CAP);
    int kcnt;
    if (cnt <= KMAX) {
        kcnt = cnt;
        for (int e = tid; e < cnt; e += blockDim.x) ssel[e] = sj[e];
    } else {
        kcnt = KMAX;
        for (int e = tid; e < cnt; e += blockDim.x) {
            float m2 = sd2[e]; int mj = sj[e]; int rank = 0;
            for (int q = 0; q < cnt; q++) {
                float o2 = sd2[q];
                rank += (o2 < m2) || (o2 == m2 && sj[q] < mj);
            }
            if (rank < KMAX) { int p = atomicAdd(&skeep, 1); ssel[p] = mj; }
        }
    }
    __syncthreads();
    if (tid == 0) cnt_out[i] = kcnt;

    const float EPS = 1e-12f;
    const float FP  = (float)(4.0 / 3.14159265358979323846);

    for (int k = tid; k < kcnt; k += blockDim.x) {
        int j = ssel[k];
        float rx = (pin[3 * j + 0] - qx) / RADIUS;
        float ry = (pin[3 * j + 1] - qy) / RADIUS;
        float rz = (pin[3 * j + 2] - qz) / RADIUS;

        float sq = rx * rx + ry * ry + rz * rz;
        float p1m = 1.0f - sq;
        float win = p1m * p1m * p1m;
        win = fminf(fmaxf(win, 0.f), 1.f);

        float nrm  = sqrtf(sq);
        float rxy2 = rx * rx + ry * ry;
        bool  polar = (1.25f * rz * rz) > rxy2;
        float s_pol = sqrtf(3.0f * nrm / (nrm + fabsf(rz) + EPS));
        float s_eq  = nrm / sqrtf(rxy2 + EPS);
        float xc = polar ? s_pol * rx : s_eq * rx;
        float yc = polar ? s_pol * ry : s_eq * ry;
        float zc = polar ? fsign(rz) * nrm : 1.5f * rz * s_eq;
        if (sq < 1e-12f) { xc = 0.f; yc = 0.f; zc = 0.f; }

        float rxy = sqrtf(xc * xc + yc * yc);
        float sx = (fabsf(xc) < EPS) ? EPS : xc;
        float sy = (fabsf(yc) < EPS) ? EPS : yc;
        float u1 = fsign(xc) * rxy;
        float v1 = u1 * FP * atanf(yc / sx);
        float v2 = fsign(yc) * rxy;
        float u2 = v2 * FP * atanf(xc / sy);
        float u, v;
        if (fabsf(xc) >= fabsf(yc)) { u = u1; v = v1; } else { u = u2; v = v2; }
        if (rxy < EPS) { u = 0.f; v = 0.f; }

        float gx = fminf(fmaxf((u  + 1.0f) * 0.5f * (float)(KS - 1), 0.f), (float)(KS - 1));
        float gy = fminf(fmaxf((v  + 1.0f) * 0.5f * (float)(KS - 1), 0.f), (float)(KS - 1));
        float gz = fminf(fmaxf((zc + 1.0f) * 0.5f * (float)(KS - 1), 0.f), (float)(KS - 1));
        int ix = min((int)floorf(gx), KS - 2);
        int iy = min((int)floorf(gy), KS - 2);
        int iz = min((int)floorf(gz), KS - 2);
        float tx = gx - (float)ix, ty = gy - (float)iy, tz = gz - (float)iz;

        int slot = i * KMAX + k;
        idx_out[slot]  = j;
        cell_out[slot] = (iz * KS + iy) * KS + ix;

        float wx[2] = {1.f - tx, tx};
        float wy[2] = {1.f - ty, ty};
        float wz[2] = {1.f - tz, tz};
        float* cf = coef_out + (size_t)slot * 8;
        #pragma unroll
        for (int dx = 0; dx < 2; dx++)
            #pragma unroll
            for (int dy = 0; dy < 2; dy++)
                #pragma unroll
                for (int dz = 0; dz < 2; dz++)
                    cf[dx * 4 + dy * 2 + dz] = wx[dx] * wy[dy] * wz[dz] * win;
    }
}

// ---------------------------------------------------------------------------
// convertW: build fp16 transposed weights Wt[n][k] for both HMMA layers.
// Tiles of 32 k-rows; layer1 tiles [0,195), layer2 tiles [195, 325).
// ---------------------------------------------------------------------------
__global__ void convertW(const float* __restrict__ c1w, const float* __restrict__ d1w,
                         const float* __restrict__ c2w, const float* __restrict__ d2w) {
    __shared__ float s[32][65];
    int t = blockIdx.x;
    const float *Wa, *Wb;
    __half* Wt;
    int K, Ka, k0;
    if (t < K1TOT / 32) {
        k0 = t * 32; K = K1TOT; Ka = 6144; Wa = c1w; Wb = d1w; Wt = g_Wt1;
    } else {
        k0 = (t - K1TOT / 32) * 32; K = K2TOT; Ka = 4096; Wa = c2w; Wb = d2w; Wt = g_Wt2;
    }
    int tid = threadIdx.x;
    #pragma unroll
    for (int i = 0; i < 8; i++) {
        int idx = tid + i * 256;          // 0..2047
        int row = idx >> 6;               // k offset 0..31
        int col = idx & 63;               // n
        int k = k0 + row;
        float v = (k < Ka) ? Wa[(size_t)k * 64 + col] : Wb[(size_t)(k - Ka) * 64 + col];
        s[row][col] = v;
    }
    __syncthreads();
    #pragma unroll
    for (int i = 0; i < 8; i++) {
        int idx = tid + i * 256;
        int n  = idx >> 5;                // 0..63
        int kk = idx & 31;
        Wt[(size_t)n * K + k0 + kk] = __float2half_rn(s[kk][n]);
    }
}

// ---------------------------------------------------------------------------
// prep: ff = [1,vel]; x96[:,64:96] = ff @ d0_w + d0_b
// ---------------------------------------------------------------------------
__global__ void prep_kernel(const float* __restrict__ vel,
                            const float* __restrict__ d0_w, const float* __restrict__ d0_b) {
    int i = blockIdx.x * blockDim.x + threadIdx.x;
    if (i >= NQ) return;
    float f1 = vel[i * 3 + 0], f2 = vel[i * 3 + 1], f3 = vel[i * 3 + 2];
    g_ff[i * 4 + 0] = 1.0f;
    g_ff[i * 4 + 1] = f1;
    g_ff[i * 4 + 2] = f2;
    g_ff[i * 4 + 3] = f3;
    #pragma unroll 8
    for (int o = 0; o < 32; o++) {
        g_x96[i * 96 + 64 + o] = d0_w[o] + f1 * d0_w[32 + o] + f2 * d0_w[64 + o]
                                 + f3 * d0_w[96 + o] + d0_b[o];
    }
}

// ---------------------------------------------------------------------------
// Scatter with k-split, fp32 smem accumulation, fp16 writeout.
// ---------------------------------------------------------------------------
template <int F, int SPLIT, int EXTRA>
__global__ void scatter_split(const int* __restrict__ cnt, const int* __restrict__ nidx,
                              const int* __restrict__ ncell, const float* __restrict__ ncoef,
                              const float* __restrict__ feats, int doRelu,
                              __half* __restrict__ Sout, int ldS) {
    int i = blockIdx.x;
    extern __shared__ float shS[];            // SPLIT * 64 * F
    __shared__ float shC[KMAX * 8];
    __shared__ int   shI[KMAX];
    __shared__ int   shCe[KMAX];
    int tid = threadIdx.x;
    const int NT = F * SPLIT;
    const int nF = 64 * F;

    for (int q = tid; q < SPLIT * nF; q += NT) shS[q] = 0.f;
    int c = cnt[i];
    for (int q = tid; q < c; q += NT) {
        shI[q]  = nidx[i * KMAX + q];
        shCe[q] = ncell[i * KMAX + q];
    }
    for (int q = tid; q < c * 8; q += NT)
        shC[q] = ncoef[(size_t)i * KMAX * 8 + q];
    __syncthreads();

    {
        int f = tid % F;
        int s = tid / F;
        int k0 = (c * s) / SPLIT;
        int k1 = (c * (s + 1)) / SPLIT;
        float* my = shS + s * nF;
        const int OFF[8] = {0, 16, 4, 20, 1, 17, 5, 21};
        for (int k = k0; k < k1; k++) {
            int j = shI[k];
            float vv = feats[(size_t)j * F + f];
            if (doRelu) vv = fmaxf(vv, 0.f);
            int base = shCe[k] * F + f;
            #pragma unroll
            for (int cc = 0; cc < 8; cc++)
                my[base + OFF[cc] * F] += shC[k * 8 + cc] * vv;
        }
    }
    __syncthreads();

    __half* dst = Sout + (size_t)i * ldS;
    for (int q = tid * 2; q < nF; q += NT * 2) {
        float v0 = shS[q], v1 = shS[q + 1];
        #pragma unroll
        for (int s = 1; s < SPLIT; s++) { v0 += shS[s * nF + q]; v1 += shS[s * nF + q + 1]; }
        *(__half2*)(dst + q) = __floats2half2_rn(v0, v1);
    }
    if (EXTRA) {
        for (int f = tid; f < F; f += NT) {
            float v = feats[(size_t)i * F + f];
            if (doRelu) v = fmaxf(v, 0.f);
            dst[nF + f] = __float2half_rn(v);
        }
    }
}

// ---------------------------------------------------------------------------
// HMMA GEMM: out[M,64] = A[M,K](fp16) @ Wt^T (Wt is [64][K] fp16) + b1 + b2 (+res)
// BM=64, BN=64, BK=32; 128 threads = 4 warps (2x2), warp tile 32x32.
// Double-buffered smem, 1 sync/iter. Fragment maps: standard m16n8k16.
// ---------------------------------------------------------------------------
#define PITCH 40   // halves per smem row

__global__ void gemm_hmma(const __half* __restrict__ A, int M, int K,
                          const __half* __restrict__ Wt,
                          const float* __restrict__ b1, const float* __restrict__ b2,
                          const float* __restrict__ res, float* __restrict__ out) {
    __shared__ __half sA[2][64 * PITCH];
    __shared__ __half sB[2][64 * PITCH];

    int tid = threadIdx.x;
    int warp = tid >> 5, lane = tid & 31;
    int g = lane >> 2, tq = lane & 3;
    int wm = (warp & 1) * 32, wn = (warp >> 1) * 32;
    int bm = blockIdx.x * 64;

    // global load mapping: chunks c = tid*2 + {0,1}; row = c>>2, colchunk = c&3 (8 halves)
    int c0 = tid * 2, c1 = c0 + 1;
    int rA0 = c0 >> 2, ch0 = c0 & 3;
    int rA1 = c1 >> 2, ch1 = c1 & 3;
    bool ok0 = (bm + rA0) < M, ok1 = (bm + rA1) < M;
    const __half* Ab0 = A + (size_t)(bm + rA0) * K + ch0 * 8;
    const __half* Ab1 = A + (size_t)(bm + rA1) * K + ch1 * 8;
    const __half* Wb0 = Wt + (size_t)rA0 * K + ch0 * 8;
    const __half* Wb1 = Wt + (size_t)rA1 * K + ch1 * 8;

    float4 acc[2][4];
    #pragma unroll
    for (int i = 0; i < 2; i++)
        #pragma unroll
        for (int j = 0; j < 4; j++) acc[i][j] = make_float4(0.f, 0.f, 0.f, 0.f);

    const uint4 Z = make_uint4(0u, 0u, 0u, 0u);
    uint4 ra0, ra1, rb0, rb1;

    // prologue: tile 0
    ra0 = ok0 ? *(const uint4*)(Ab0) : Z;
    ra1 = ok1 ? *(const uint4*)(Ab1) : Z;
    rb0 = *(const uint4*)(Wb0);
    rb1 = *(const uint4*)(Wb1);
    *(uint4*)&sA[0][rA0 * PITCH + ch0 * 8] = ra0;
    *(uint4*)&sA[0][rA1 * PITCH + ch1 * 8] = ra1;
    *(uint4*)&sB[0][rA0 * PITCH + ch0 * 8] = rb0;
    *(uint4*)&sB[0][rA1 * PITCH + ch1 * 8] = rb1;
    __syncthreads();

    int nt = K / 32;
    for (int t = 0; t < nt; t++) {
        int cur = t & 1;
        if (t + 1 < nt) {
            int kt = (t + 1) * 32;
            ra0 = ok0 ? *(const uint4*)(Ab0 + kt) : Z;
            ra1 = ok1 ? *(const uint4*)(Ab1 + kt) : Z;
            rb0 = *(const uint4*)(Wb0 + kt);
            rb1 = *(const uint4*)(Wb1 + kt);
        }

        const __half* cA = sA[cur];
        const __half* cB = sB[cur];
        #pragma unroll
        for (int ks = 0; ks < 32; ks += 16) {
            unsigned af[2][4], bf[4][2];
            #pragma unroll
            for (int mi = 0; mi < 2; mi++) {
                int rbase = (wm + mi * 16 + g) * PITCH + ks + 2 * tq;
                af[mi][0] = *(const unsigned*)&cA[rbase];
                af[mi][1] = *(const unsigned*)&cA[rbase + 8 * PITCH];
                af[mi][2] = *(const unsigned*)&cA[rbase + 8];
                af[mi][3] = *(const unsigned*)&cA[rbase + 8 * PITCH + 8];
            }
            #pragma unroll
            for (int nj = 0; nj < 4; nj++) {
                int nbase = (wn + nj * 8 + g) * PITCH + ks + 2 * tq;
                bf[nj][0] = *(const unsigned*)&cB[nbase];
                bf[nj][1] = *(const unsigned*)&cB[nbase + 8];
            }
            #pragma unroll
            for (int mi = 0; mi < 2; mi++)
                #pragma unroll
                for (int nj = 0; nj < 4; nj++)
                    mma16816(acc[mi][nj], af[mi][0], af[mi][1], af[mi][2], af[mi][3],
                             bf[nj][0], bf[nj][1]);
        }

        if (t + 1 < nt) {
            int nxt = cur ^ 1;
            *(uint4*)&sA[nxt][rA0 * PITCH + ch0 * 8] = ra0;
            *(uint4*)&sA[nxt][rA1 * PITCH + ch1 * 8] = ra1;
            *(uint4*)&sB[nxt][rA0 * PITCH + ch0 * 8] = rb0;
            *(uint4*)&sB[nxt][rA1 * PITCH + ch1 * 8] = rb1;
            __syncthreads();
        }
    }

    // epilogue: bias (+ residual), fp32 out
    #pragma unroll
    for (int mi = 0; mi < 2; mi++) {
        int r0 = bm + wm + mi * 16 + g;
        int r1 = r0 + 8;
        #pragma unroll
        for (int nj = 0; nj < 4; nj++) {
            int col = wn + nj * 8 + 2 * tq;
            float bb0 = b1[col] + b2[col];
            float bb1 = b1[col + 1] + b2[col + 1];
            float4 d = acc[mi][nj];
            if (r0 < M) {
                float vx = d.x + bb0, vy = d.y + bb1;
                if (res) { vx += res[(size_t)r0 * 64 + col]; vy += res[(size_t)r0 * 64 + col + 1]; }
                *(float2*)&out[(size_t)r0 * 64 + col] = make_float2(vx, vy);
            }
            if (r1 < M) {
                float vx = d.z + bb0, vy = d.w + bb1;
                if (res) { vx += res[(size_t)r1 * 64 + col]; vy += res[(size_t)r1 * 64 + col + 1]; }
                *(float2*)&out[(size_t)r1 * 64 + col] = make_float2(vx, vy);
            }
        }
    }
}

// ---------------------------------------------------------------------------
// Small-O GEMM, fp16 A, transposed padded W cache [O][K+1] (conflict-free).
// out = (A @ [W1;W2] + bias1 + bias2) * scale
// ---------------------------------------------------------------------------
template <int O>
__global__ void gemm_small(const __half* __restrict__ A, int lda, int M,
                           int K1, const float* __restrict__ W1,
                           int K2, const float* __restrict__ W2,
                           const float* __restrict__ bias1, const float* __restrict__ bias2,
                           float* __restrict__ out, int ldo, int ooff, float scale) {
    extern __shared__ float sW[];   // O * (K+1), transposed
    int tid = threadIdx.x;
    int K = K1 + K2;
    int KP = K + 1;
    for (int q = tid; q < K1 * O; q += blockDim.x) {
        int k = q / O, o = q - k * O;
        sW[o * KP + k] = W1[q];
    }
    for (int q = tid; q < K2 * O; q += blockDim.x) {
        int k = q / O, o = q - k * O;
        sW[o * KP + K1 + k] = W2[q];
    }
    __syncthreads();

    int warp = blockIdx.x * (blockDim.x >> 5) + (tid >> 5);
    int lane = tid & 31;
    if (warp >= M) return;
    const __half* Ar = A + (size_t)warp * lda;

    float acc[O];
    #pragma unroll
    for (int o = 0; o < O; o++) acc[o] = 0.f;

    for (int k = lane * 2; k < K; k += 64) {
        float2 a = __half22float2(*(const __half2*)(Ar + k));
        #pragma unroll
        for (int o = 0; o < O; o++)
            acc[o] += a.x * sW[o * KP + k] + a.y * sW[o * KP + k + 1];
    }

    float myv = 0.f;
    #pragma unroll
    for (int o = 0; o < O; o++) {
        float v = acc[o];
        v += __shfl_xor_sync(0xffffffffu, v, 16);
        v += __shfl_xor_sync(0xffffffffu, v, 8);
        v += __shfl_xor_sync(0xffffffffu, v, 4);
        v += __shfl_xor_sync(0xffffffffu, v, 2);
        v += __shfl_xor_sync(0xffffffffu, v, 1);
        if (lane == o) myv = v;
    }
    if (lane < O) {
        float r = myv + (bias1 ? bias1[lane] : 0.f) + (bias2 ? bias2[lane] : 0.f);
        out[(size_t)warp * ldo + ooff + lane] = r * scale;
    }
}

// ---------------------------------------------------------------------------
// Host launch
// ---------------------------------------------------------------------------
template <typename T>
static T* symaddr(const void* sym) {
    void* p = nullptr;
    cudaGetSymbolAddress(&p, sym);
    return (T*)p;
}

extern "C" void kernel_launch(void* const* d_in, const int* in_sizes, int n_in,
                              void* d_out, int out_size) {
    cudaFuncSetAttribute(scatter_split<96, 2, 1>, cudaFuncAttributeMaxDynamicSharedMemorySize, 64 * 1024);
    cudaFuncSetAttribute(scatter_split<64, 3, 1>, cudaFuncAttributeMaxDynamicSharedMemorySize, 64 * 1024);
    cudaFuncSetAttribute(scatter_split<4, 32, 0>, cudaFuncAttributeMaxDynamicSharedMemorySize, 64 * 1024);
    cudaFuncSetAttribute(scatter_split<3, 32, 0>, cudaFuncAttributeMaxDynamicSharedMemorySize, 64 * 1024);
    cudaFuncSetAttribute(gemm_small<3>, cudaFuncAttributeMaxDynamicSharedMemorySize, 64 * 1024);
    cudaFuncSetAttribute(gemm_small<32>, cudaFuncAttributeMaxDynamicSharedMemorySize, 64 * 1024);

    const float* pos       = (const float*)d_in[0];
    const float* vel       = (const float*)d_in[1];
    const float* box       = (const float*)d_in[2];
    const float* box_feats = (const float*)d_in[3];
    const float* cf_w = (const float*)d_in[4];
    const float* cf_b = (const float*)d_in[5];
    const float* co_w = (const float*)d_in[6];
    const float* co_b = (const float*)d_in[7];
    const float* d0_w = (const float*)d_in[8];
    const float* d0_b = (const float*)d_in[9];
    const float* c1_w = (const float*)d_in[10];
    const float* c1_b = (const float*)d_in[11];
    const float* d1_w = (const float*)d_in[12];
    const float* d1_b = (const float*)d_in[13];
    const float* c2_w = (const float*)d_in[14];
    const float* c2_b = (const float*)d_in[15];
    const float* d2_w = (const float*)d_in[16];
    const float* d2_b = (const float*)d_in[17];
    const float* c3_w = (const float*)d_in[18];
    const float* c3_b = (const float*)d_in[19];
    const float* d3_w = (const float*)d_in[20];
    const float* d3_b = (const float*)d_in[21];
    float* out = (float*)d_out;

    __half* S   = symaddr<__half>(g_S);
    float* x96  = symaddr<float>(g_x96);
    float* ya   = symaddr<float>(g_ya);
    float* yb   = symaddr<float>(g_yb);
    float* ff   = symaddr<float>(g_ff);
    __half* Wt1 = symaddr<__half>(g_Wt1);
    __half* Wt2 = symaddr<__half>(g_Wt2);
    int*   fcnt  = symaddr<int>(g_fcnt);
    int*   fidx  = symaddr<int>(g_fidx);
    int*   fcell = symaddr<int>(g_fcell);
    float* fcoef = symaddr<float>(g_fcoef);
    int*   ocnt  = symaddr<int>(g_ocnt);
    int*   oidx  = symaddr<int>(g_oidx);
    int*   ocell = symaddr<int>(g_ocell);
    float* ocoef = symaddr<float>(g_ocoef);

    const int M = NQ;

    // 0-2) hash grids
    dim3 gh((NQ + 255) / 256, 2);
    grid_hist2<<<gh, 256>>>(pos, box);                          // idx 0
    grid_scan2<<<2, NCELLS>>>();                                // idx 1
    grid_fill2<<<gh, 256>>>(pos, box);                          // idx 2

    // 3) neighbor search (ncu profiled slot)
    dim3 gn(NQ, 2);
    nbr_grid2<<<gn, 128>>>(pos, box);                           // idx 3

    // 4-5) weight convert + prep (independent)
    convertW<<<(K1TOT + K2TOT) / 32, 256>>>(c1_w, d1_w, c2_w, d2_w);
    prep_kernel<<<(NQ + 255) / 256, 256>>>(vel, d0_w, d0_b);

    // 6) first block: x96 = [a_co | a_cf | a_d0]
    scatter_split<4, 32, 0><<<NQ, 128, 32 * 64 * 4 * 4>>>(fcnt, fidx, fcell, fcoef, ff, 0, S, 256);
    gemm_small<32><<<(M + 7) / 8, 256, 257 * 32 * 4>>>(S, 256, M, 256, cf_w, 0, nullptr, cf_b, nullptr, x96, 96, 32, 1.f);
    scatter_split<3, 32, 0><<<NQ, 96, 32 * 64 * 3 * 4>>>(ocnt, oidx, ocell, ocoef, box_feats, 0, S, 192);
    gemm_small<32><<<(M + 7) / 8, 256, 193 * 32 * 4>>>(S, 192, M, 192, co_w, 0, nullptr, co_b, nullptr, x96, 96, 0, 1.f);

    dim3 gg((M + 63) / 64);

    // 7) layer 1: ya = S1 @ [c1_w; d1_w] + c1_b + d1_b   (tensor cores)
    scatter_split<96, 2, 1><<<NQ, 192, 2 * 64 * 96 * 4>>>(fcnt, fidx, fcell, fcoef, x96, 1, S, K1TOT);
    gemm_hmma<<<gg, 128>>>(S, M, K1TOT, Wt1, c1_b, d1_b, nullptr, ya);

    // 8) layer 2: yb = S2 @ [c2_w; d2_w] + c2_b + d2_b + ya
    scatter_split<64, 3, 1><<<NQ, 192, 3 * 64 * 64 * 4>>>(fcnt, fidx, fcell, fcoef, ya, 1, S, K2TOT);
    gemm_hmma<<<gg, 128>>>(S, M, K2TOT, Wt2, c2_b, d2_b, ya, yb);

    // 9) layer 3: out = (S3 @ [c3_w; d3_w] + c3_b + d3_b) / 128
    scatter_split<64, 3, 1><<<NQ, 192, 3 * 64 * 64 * 4>>>(fcnt, fidx, fcell, fcoef, yb, 1, S, K2TOT);
    gemm_small<3><<<(M + 7) / 8, 256, 4161 * 3 * 4>>>(S, K2TOT, M, 4096, c3_w, 64, d3_w, c3_b, d3_b, out, 3, 0, 1.0f / 128.0f);
}

// round 11
// speedup vs baseline: 1.7833x; 1.1906x over previous
#include <cuda_runtime.h>
#include <cuda_bf16.h>
#include <cuda_fp16.h>
#include <math.h>

// ---------------------------------------------------------------------------
// Problem constants
// ---------------------------------------------------------------------------
#define NQ      6000
#define NBOX    3000
#define KMAX    80
#define CAP     256
#define KS      4
#define NCELL   64
#define RADIUS  0.1125f

#define GDIM    8
#define NCELLS  (GDIM*GDIM*GDIM)

#define K1TOT   6240     // layer1 GEMM K (6144 conv + 96 dense)
#define K2TOT   4160     // layer2 GEMM K (4096 conv + 64 dense)

// ---------------------------------------------------------------------------
// Device scratch
// ---------------------------------------------------------------------------
__device__ __align__(16) __half g_S[(size_t)NQ * K1TOT];
__device__ __align__(16) float g_x96[NQ * 96];
__device__ __align__(16) float g_ya[NQ * 64];
__device__ __align__(16) float g_yb[NQ * 64];
__device__ __align__(16) float g_ff[NQ * 4];
__device__ __align__(16) __half g_Wt1[64 * K1TOT];   // [n][k] fp16, layer1
__device__ __align__(16) __half g_Wt2[64 * K2TOT];   // [n][k] fp16, layer2

__device__ int   g_fcnt[NQ];
__device__ int   g_fidx[NQ * KMAX];
__device__ int   g_fcell[NQ * KMAX];
__device__ __align__(16) float g_fcoef[(size_t)NQ * KMAX * 8];

__device__ int   g_ocnt[NQ];
__device__ int   g_oidx[NQ * KMAX];
__device__ int   g_ocell[NQ * KMAX];
__device__ __align__(16) float g_ocoef[(size_t)NQ * KMAX * 8];

// hash grids (0 = fluid/pos, 1 = box); counters self-re-zeroed in grid_scan2
__device__ int g_gcnt[2][NCELLS];
__device__ int g_gstart[2][NCELLS + 1];
__device__ int g_gcur[2][NCELLS];
__device__ int g_glistF[NQ];
__device__ int g_glistB[NBOX];

// ---------------------------------------------------------------------------
// Helpers
// ---------------------------------------------------------------------------
__device__ __forceinline__ float fsign(float x) {
    return (x > 0.f) ? 1.f : ((x < 0.f) ? -1.f : 0.f);
}

__device__ __forceinline__ int cell_coord(float x) {
    int c = (int)(x * (float)GDIM);
    return min(max(c, 0), GDIM - 1);
}

__device__ __forceinline__ void mma16816(float4& d, unsigned a0, unsigned a1,
                                         unsigned a2, unsigned a3,
                                         unsigned b0, unsigned b1) {
    asm volatile(
        "mma.sync.aligned.m16n8k16.row.col.f32.f16.f16.f32 "
        "{%0,%1,%2,%3}, {%4,%5,%6,%7}, {%8,%9}, {%0,%1,%2,%3};"
        : "+f"(d.x), "+f"(d.y), "+f"(d.z), "+f"(d.w)
        : "r"(a0), "r"(a1), "r"(a2), "r"(a3), "r"(b0), "r"(b1));
}

// ---------------------------------------------------------------------------
// Hash grid build
// ---------------------------------------------------------------------------
__global__ void grid_hist2(const float* __restrict__ pos, const float* __restrict__ box) {
    int g = blockIdx.y;
    const float* p = g ? box : pos;
    int n = g ? NBOX : NQ;
    int i = blockIdx.x * blockDim.x + threadIdx.x;
    if (i >= n) return;
    int cx = cell_coord(p[3 * i + 0]);
    int cy = cell_coord(p[3 * i + 1]);
    int cz = cell_coord(p[3 * i + 2]);
    atomicAdd(&g_gcnt[g][(cz * GDIM + cy) * GDIM + cx], 1);
}

__global__ void grid_scan2() {
    int g = blockIdx.x;
    __shared__ int s[NCELLS];
    int t = threadIdx.x;
    int v = g_gcnt[g][t];
    g_gcnt[g][t] = 0;          // reset for next replay (deterministic)
    s[t] = v;
    __syncthreads();
    for (int off = 1; off < NCELLS; off <<= 1) {
        int x = (t >= off) ? s[t - off] : 0;
        __syncthreads();
        s[t] += x;
        __syncthreads();
    }
    g_gstart[g][t + 1] = s[t];
    g_gcur[g][t] = s[t] - v;
    if (t == 0) g_gstart[g][0] = 0;
}

__global__ void grid_fill2(const float* __restrict__ pos, const float* __restrict__ box) {
    int g = blockIdx.y;
    const float* p = g ? box : pos;
    int n = g ? NBOX : NQ;
    int* list = g ? g_glistB : g_glistF;
    int i = blockIdx.x * blockDim.x + threadIdx.x;
    if (i >= n) return;
    int cx = cell_coord(p[3 * i + 0]);
    int cy = cell_coord(p[3 * i + 1]);
    int cz = cell_coord(p[3 * i + 2]);
    int slot = atomicAdd(&g_gcur[g][(cz * GDIM + cy) * GDIM + cx], 1);
    list[slot] = i;
}

// ---------------------------------------------------------------------------
// Neighbor search (both passes in one launch)
// ---------------------------------------------------------------------------
__global__ void nbr_grid2(const float* __restrict__ pos, const float* __restrict__ box) {
    int pass = blockIdx.y;
    const float* pin   = pass ? box : pos;
    const int*  glist  = pass ? g_glistB : g_glistF;
    const int*  gstart = g_gstart[pass];
    int selfExcl = pass ? 0 : 1;
    int* cnt_out  = pass ? g_ocnt  : g_fcnt;
    int* idx_out  = pass ? g_oidx  : g_fidx;
    int* cell_out = pass ? g_ocell : g_fcell;
    float* coef_out = pass ? g_ocoef : g_fcoef;

    int i = blockIdx.x;
    __shared__ float sd2[CAP];
    __shared__ int   sj[CAP];
    __shared__ int   ssel[KMAX];
    __shared__ int   scnt, skeep;
    int tid = threadIdx.x;
    if (tid == 0) { scnt = 0; skeep = 0; }
    __syncthreads();

    float qx = pos[3 * i + 0], qy = pos[3 * i + 1], qz = pos[3 * i + 2];
    const float R2 = RADIUS * RADIUS;

    int cx = cell_coord(qx), cy = cell_coord(qy), cz = cell_coord(qz);
    int x0 = max(cx - 1, 0), x1 = min(cx + 1, GDIM - 1);
    int y0 = max(cy - 1, 0), y1 = min(cy + 1, GDIM - 1);
    int z0 = max(cz - 1, 0), z1 = min(cz + 1, GDIM - 1);

    for (int z = z0; z <= z1; z++) {
        for (int y = y0; y <= y1; y++) {
            int cbase = (z * GDIM + y) * GDIM;
            int b = gstart[cbase + x0];
            int e = gstart[cbase + x1 + 1];
            for (int t = b + tid; t < e; t += blockDim.x) {
                int j = glist[t];
                if (selfExcl && j == i) continue;
                float dx = pin[3 * j + 0] - qx;
                float dy = pin[3 * j + 1] - qy;
                float dz = pin[3 * j + 2] - qz;
                float d2 = dx * dx + dy * dy + dz * dz;
                if (d2 <= R2) {
                    int p = atomicAdd(&scnt, 1);
                    if (p < CAP) { sd2[p] = d2; sj[p] = j; }
                }
            }
        }
    }
    __syncthreads();

    int cnt = min(scnt, CAP);
    int kcnt;
    if (cnt <= KMAX) {
        kcnt = cnt;
        for (int e = tid; e < cnt; e += blockDim.x) ssel[e] = sj[e];
    } else {
        kcnt = KMAX;
        for (int e = tid; e < cnt; e += blockDim.x) {
            float m2 = sd2[e]; int mj = sj[e]; int rank = 0;
            for (int q = 0; q < cnt; q++) {
                float o2 = sd2[q];
                rank += (o2 < m2) || (o2 == m2 && sj[q] < mj);
            }
            if (rank < KMAX) { int p = atomicAdd(&skeep, 1); ssel[p] = mj; }
        }
    }
    __syncthreads();
    if (tid == 0) cnt_out[i] = kcnt;

    const float EPS = 1e-12f;
    const float FP  = (float)(4.0 / 3.14159265358979323846);

    for (int k = tid; k < kcnt; k += blockDim.x) {
        int j = ssel[k];
        float rx = (pin[3 * j + 0] - qx) / RADIUS;
        float ry = (pin[3 * j + 1] - qy) / RADIUS;
        float rz = (pin[3 * j + 2] - qz) / RADIUS;

        float sq = rx * rx + ry * ry + rz * rz;
        float p1m = 1.0f - sq;
        float win = p1m * p1m * p1m;
        win = fminf(fmaxf(win, 0.f), 1.f);

        float nrm  = sqrtf(sq);
        float rxy2 = rx * rx + ry * ry;
        bool  polar = (1.25f * rz * rz) > rxy2;
        float s_pol = sqrtf(3.0f * nrm / (nrm + fabsf(rz) + EPS));
        float s_eq  = nrm / sqrtf(rxy2 + EPS);
        float xc = polar ? s_pol * rx : s_eq * rx;
        float yc = polar ? s_pol * ry : s_eq * ry;
        float zc = polar ? fsign(rz) * nrm : 1.5f * rz * s_eq;
        if (sq < 1e-12f) { xc = 0.f; yc = 0.f; zc = 0.f; }

        float rxy = sqrtf(xc * xc + yc * yc);
        float sx = (fabsf(xc) < EPS) ? EPS : xc;
        float sy = (fabsf(yc) < EPS) ? EPS : yc;
        float u1 = fsign(xc) * rxy;
        float v1 = u1 * FP * atanf(yc / sx);
        float v2 = fsign(yc) * rxy;
        float u2 = v2 * FP * atanf(xc / sy);
        float u, v;
        if (fabsf(xc) >= fabsf(yc)) { u = u1; v = v1; } else { u = u2; v = v2; }
        if (rxy < EPS) { u = 0.f; v = 0.f; }

        float gx = fminf(fmaxf((u  + 1.0f) * 0.5f * (float)(KS - 1), 0.f), (float)(KS - 1));
        float gy = fminf(fmaxf((v  + 1.0f) * 0.5f * (float)(KS - 1), 0.f), (float)(KS - 1));
        float gz = fminf(fmaxf((zc + 1.0f) * 0.5f * (float)(KS - 1), 0.f), (float)(KS - 1));
        int ix = min((int)floorf(gx), KS - 2);
        int iy = min((int)floorf(gy), KS - 2);
        int iz = min((int)floorf(gz), KS - 2);
        float tx = gx - (float)ix, ty = gy - (float)iy, tz = gz - (float)iz;

        int slot = i * KMAX + k;
        idx_out[slot]  = j;
        cell_out[slot] = (iz * KS + iy) * KS + ix;

        float wx[2] = {1.f - tx, tx};
        float wy[2] = {1.f - ty, ty};
        float wz[2] = {1.f - tz, tz};
        float* cf = coef_out + (size_t)slot * 8;
        #pragma unroll
        for (int dx = 0; dx < 2; dx++)
            #pragma unroll
            for (int dy = 0; dy < 2; dy++)
                #pragma unroll
                for (int dz = 0; dz < 2; dz++)
                    cf[dx * 4 + dy * 2 + dz] = wx[dx] * wy[dy] * wz[dz] * win;
    }
}

// ---------------------------------------------------------------------------
// convertW: build fp16 transposed weights Wt[n][k] for both HMMA layers.
// ---------------------------------------------------------------------------
__global__ void convertW(const float* __restrict__ c1w, const float* __restrict__ d1w,
                         const float* __restrict__ c2w, const float* __restrict__ d2w) {
    __shared__ float s[32][65];
    int t = blockIdx.x;
    const float *Wa, *Wb;
    __half* Wt;
    int K, Ka, k0;
    if (t < K1TOT / 32) {
        k0 = t * 32; K = K1TOT; Ka = 6144; Wa = c1w; Wb = d1w; Wt = g_Wt1;
    } else {
        k0 = (t - K1TOT / 32) * 32; K = K2TOT; Ka = 4096; Wa = c2w; Wb = d2w; Wt = g_Wt2;
    }
    int tid = threadIdx.x;
    #pragma unroll
    for (int i = 0; i < 8; i++) {
        int idx = tid + i * 256;          // 0..2047
        int row = idx >> 6;               // k offset 0..31
        int col = idx & 63;               // n
        int k = k0 + row;
        float v = (k < Ka) ? Wa[(size_t)k * 64 + col] : Wb[(size_t)(k - Ka) * 64 + col];
        s[row][col] = v;
    }
    __syncthreads();
    #pragma unroll
    for (int i = 0; i < 8; i++) {
        int idx = tid + i * 256;
        int n  = idx >> 5;                // 0..63
        int kk = idx & 31;
        Wt[(size_t)n * K + k0 + kk] = __float2half_rn(s[kk][n]);
    }
}

// ---------------------------------------------------------------------------
// prep: ff = [1,vel]; x96[:,64:96] = ff @ d0_w + d0_b
// ---------------------------------------------------------------------------
__global__ void prep_kernel(const float* __restrict__ vel,
                            const float* __restrict__ d0_w, const float* __restrict__ d0_b) {
    int i = blockIdx.x * blockDim.x + threadIdx.x;
    if (i >= NQ) return;
    float f1 = vel[i * 3 + 0], f2 = vel[i * 3 + 1], f3 = vel[i * 3 + 2];
    g_ff[i * 4 + 0] = 1.0f;
    g_ff[i * 4 + 1] = f1;
    g_ff[i * 4 + 2] = f2;
    g_ff[i * 4 + 3] = f3;
    #pragma unroll 8
    for (int o = 0; o < 32; o++) {
        g_x96[i * 96 + 64 + o] = d0_w[o] + f1 * d0_w[32 + o] + f2 * d0_w[64 + o]
                                 + f3 * d0_w[96 + o] + d0_b[o];
    }
}

// ---------------------------------------------------------------------------
// Scalar scatter with k-split (kept for small F), fp32 accum, fp16 out.
// ---------------------------------------------------------------------------
template <int F, int SPLIT, int EXTRA>
__global__ void scatter_split(const int* __restrict__ cnt, const int* __restrict__ nidx,
                              const int* __restrict__ ncell, const float* __restrict__ ncoef,
                              const float* __restrict__ feats, int doRelu,
                              __half* __restrict__ Sout, int ldS) {
    int i = blockIdx.x;
    extern __shared__ float shS[];            // SPLIT * 64 * F
    __shared__ float shC[KMAX * 8];
    __shared__ int   shI[KMAX];
    __shared__ int   shCe[KMAX];
    int tid = threadIdx.x;
    const int NT = F * SPLIT;
    const int nF = 64 * F;

    for (int q = tid; q < SPLIT * nF; q += NT) shS[q] = 0.f;
    int c = cnt[i];
    for (int q = tid; q < c; q += NT) {
        shI[q]  = nidx[i * KMAX + q];
        shCe[q] = ncell[i * KMAX + q];
    }
    for (int q = tid; q < c * 8; q += NT)
        shC[q] = ncoef[(size_t)i * KMAX * 8 + q];
    __syncthreads();

    {
        int f = tid % F;
        int s = tid / F;
        int k0 = (c * s) / SPLIT;
        int k1 = (c * (s + 1)) / SPLIT;
        float* my = shS + s * nF;
        const int OFF[8] = {0, 16, 4, 20, 1, 17, 5, 21};
        for (int k = k0; k < k1; k++) {
            int j = shI[k];
            float vv = feats[(size_t)j * F + f];
            if (doRelu) vv = fmaxf(vv, 0.f);
            int base = shCe[k] * F + f;
            #pragma unroll
            for (int cc = 0; cc < 8; cc++)
                my[base + OFF[cc] * F] += shC[k * 8 + cc] * vv;
        }
    }
    __syncthreads();

    __half* dst = Sout + (size_t)i * ldS;
    for (int q = tid * 2; q < nF; q += NT * 2) {
        float v0 = shS[q], v1 = shS[q + 1];
        #pragma unroll
        for (int s = 1; s < SPLIT; s++) { v0 += shS[s * nF + q]; v1 += shS[s * nF + q + 1]; }
        *(__half2*)(dst + q) = __floats2half2_rn(v0, v1);
    }
    if (EXTRA) {
        for (int f = tid; f < F; f += NT) {
            float v = feats[(size_t)i * F + f];
            if (doRelu) v = fmaxf(v, 0.f);
            dst[nF + f] = __float2half_rn(v);
        }
    }
}

// ---------------------------------------------------------------------------
// Tensor-core scatter: S_row[64,F] = CoefDense[64,80] @ NF[80,F] per particle.
// One block (128 thr, 4 warps) per particle. A = dense trilinear coefs (fp16),
// B = gathered neighbor feats transposed to [f][k] (fp16). m16n8k16, fp32 acc.
// Row layout written to gmem: [64*F scatter | F appended relu(feats[i])].
// ---------------------------------------------------------------------------
#define PA 82   // smem pitch in halves (odd word stride -> conflict-free columns)

template <int F>
__global__ void scatter_mma(const int* __restrict__ cnt, const int* __restrict__ nidx,
                            const int* __restrict__ ncell, const float* __restrict__ ncoef,
                            const float* __restrict__ feats,
                            __half* __restrict__ Sout, int ldS) {
    __shared__ __half sA[64 * PA];      // coef dense [cell][k]
    __shared__ __half sB[F * PA];       // feats transposed [f][k]
    __shared__ float shC[KMAX * 8];
    __shared__ int   shI[KMAX];

    int i = blockIdx.x;
    int tid = threadIdx.x;
    int warp = tid >> 5, lane = tid & 31;
    int g = lane >> 2, tq = lane & 3;

    // zero both operands (c<80 columns must be exactly 0; avoids 0*garbage=NaN)
    unsigned* za = (unsigned*)sA;
    unsigned* zb = (unsigned*)sB;
    for (int q = tid; q < 64 * PA / 2; q += 128) za[q] = 0u;
    for (int q = tid; q < F * PA / 2; q += 128) zb[q] = 0u;

    int c = cnt[i];
    for (int q = tid; q < c; q += 128) shI[q] = nidx[i * KMAX + q];
    for (int q = tid; q < c * 8; q += 128) shC[q] = ncoef[(size_t)i * KMAX * 8 + q];
    __syncthreads();

    // build A: 8 corner coefs per neighbor column
    {
        const int OFF[8] = {0, 16, 4, 20, 1, 17, 5, 21};
        __shared__ int shCe[KMAX];
        for (int q = tid; q < c; q += 128) shCe[q] = ncell[i * KMAX + q];
        __syncthreads();
        for (int t = tid; t < c * 8; t += 128) {
            int k = t >> 3, cc = t & 7;
            sA[(shCe[k] + OFF[cc]) * PA + k] = __float2half_rn(shC[t]);
        }
    }

    // gather B: NFt[f][k] = relu(feats[shI[k]][f])
    for (int k = warp; k < c; k += 4) {
        const float* fr = feats + (size_t)shI[k] * F;
        #pragma unroll
        for (int f = lane; f < F; f += 32)
            sB[f * PA + k] = __float2half_rn(fmaxf(fr[f], 0.f));
    }
    __syncthreads();

    // mma: warp handles cells [warp*16, warp*16+16), all F columns
    float4 acc[F / 8];
    #pragma unroll
    for (int nj = 0; nj < F / 8; nj++) acc[nj] = make_float4(0.f, 0.f, 0.f, 0.f);

    #pragma unroll
    for (int ks = 0; ks < KMAX; ks += 16) {
        int rbase = (warp * 16 + g) * PA + ks + 2 * tq;
        unsigned a0 = *(const unsigned*)&sA[rbase];
        unsigned a1 = *(const unsigned*)&sA[rbase + 8 * PA];
        unsigned a2 = *(const unsigned*)&sA[rbase + 8];
        unsigned a3 = *(const unsigned*)&sA[rbase + 8 * PA + 8];
        #pragma unroll
        for (int nj = 0; nj < F / 8; nj++) {
            int nbase = (nj * 8 + g) * PA + ks + 2 * tq;
            unsigned b0 = *(const unsigned*)&sB[nbase];
            unsigned b1 = *(const unsigned*)&sB[nbase + 8];
            mma16816(acc[nj], a0, a1, a2, a3, b0, b1);
        }
    }

    // epilogue: S[cell][f], fp16
    __half* dst = Sout + (size_t)i * ldS;
    int r0 = warp * 16 + g, r1 = r0 + 8;
    #pragma unroll
    for (int nj = 0; nj < F / 8; nj++) {
        int col = nj * 8 + 2 * tq;
        *(__half2*)(dst + r0 * F + col) = __floats2half2_rn(acc[nj].x, acc[nj].y);
        *(__half2*)(dst + r1 * F + col) = __floats2half2_rn(acc[nj].z, acc[nj].w);
    }
    // appended dense-branch columns
    if (tid < F)
        dst[64 * F + tid] = __float2half_rn(fmaxf(feats[(size_t)i * F + tid], 0.f));
}

// ---------------------------------------------------------------------------
// HMMA GEMM: out[M,64] = A[M,K](fp16) @ Wt^T + b1 + b2 (+res)
// BM=64, BN=64, BK=32; 128 threads = 4 warps (2x2), warp tile 32x32.
// ---------------------------------------------------------------------------
#define PITCH 40   // halves per smem row

__global__ void gemm_hmma(const __half* __restrict__ A, int M, int K,
                          const __half* __restrict__ Wt,
                          const float* __restrict__ b1, const float* __restrict__ b2,
                          const float* __restrict__ res, float* __restrict__ out) {
    __shared__ __half sA[2][64 * PITCH];
    __shared__ __half sB[2][64 * PITCH];

    int tid = threadIdx.x;
    int warp = tid >> 5, lane = tid & 31;
    int g = lane >> 2, tq = lane & 3;
    int wm = (warp & 1) * 32, wn = (warp >> 1) * 32;
    int bm = blockIdx.x * 64;

    int c0 = tid * 2, c1 = c0 + 1;
    int rA0 = c0 >> 2, ch0 = c0 & 3;
    int rA1 = c1 >> 2, ch1 = c1 & 3;
    bool ok0 = (bm + rA0) < M, ok1 = (bm + rA1) < M;
    const __half* Ab0 = A + (size_t)(bm + rA0) * K + ch0 * 8;
    const __half* Ab1 = A + (size_t)(bm + rA1) * K + ch1 * 8;
    const __half* Wb0 = Wt + (size_t)rA0 * K + ch0 * 8;
    const __half* Wb1 = Wt + (size_t)rA1 * K + ch1 * 8;

    float4 acc[2][4];
    #pragma unroll
    for (int i = 0; i < 2; i++)
        #pragma unroll
        for (int j = 0; j < 4; j++) acc[i][j] = make_float4(0.f, 0.f, 0.f, 0.f);

    const uint4 Z = make_uint4(0u, 0u, 0u, 0u);
    uint4 ra0, ra1, rb0, rb1;

    ra0 = ok0 ? *(const uint4*)(Ab0) : Z;
    ra1 = ok1 ? *(const uint4*)(Ab1) : Z;
    rb0 = *(const uint4*)(Wb0);
    rb1 = *(const uint4*)(Wb1);
    *(uint4*)&sA[0][rA0 * PITCH + ch0 * 8] = ra0;
    *(uint4*)&sA[0][rA1 * PITCH + ch1 * 8] = ra1;
    *(uint4*)&sB[0][rA0 * PITCH + ch0 * 8] = rb0;
    *(uint4*)&sB[0][rA1 * PITCH + ch1 * 8] = rb1;
    __syncthreads();

    int nt = K / 32;
    for (int t = 0; t < nt; t++) {
        int cur = t & 1;
        if (t + 1 < nt) {
            int kt = (t + 1) * 32;
            ra0 = ok0 ? *(const uint4*)(Ab0 + kt) : Z;
            ra1 = ok1 ? *(const uint4*)(Ab1 + kt) : Z;
            rb0 = *(const uint4*)(Wb0 + kt);
            rb1 = *(const uint4*)(Wb1 + kt);
        }

        const __half* cA = sA[cur];
        const __half* cB = sB[cur];
        #pragma unroll
        for (int ks = 0; ks < 32; ks += 16) {
            unsigned af[2][4], bf[4][2];
            #pragma unroll
            for (int mi = 0; mi < 2; mi++) {
                int rbase = (wm + mi * 16 + g) * PITCH + ks + 2 * tq;
                af[mi][0] = *(const unsigned*)&cA[rbase];
                af[mi][1] = *(const unsigned*)&cA[rbase + 8 * PITCH];
                af[mi][2] = *(const unsigned*)&cA[rbase + 8];
                af[mi][3] = *(const unsigned*)&cA[rbase + 8 * PITCH + 8];
            }
            #pragma unroll
            for (int nj = 0; nj < 4; nj++) {
                int nbase = (wn + nj * 8 + g) * PITCH + ks + 2 * tq;
                bf[nj][0] = *(const unsigned*)&cB[nbase];
                bf[nj][1] = *(const unsigned*)&cB[nbase + 8];
            }
            #pragma unroll
            for (int mi = 0; mi < 2; mi++)
                #pragma unroll
                for (int nj = 0; nj < 4; nj++)
                    mma16816(acc[mi][nj], af[mi][0], af[mi][1], af[mi][2], af[mi][3],
                             bf[nj][0], bf[nj][1]);
        }

        if (t + 1 < nt) {
            int nxt = cur ^ 1;
            *(uint4*)&sA[nxt][rA0 * PITCH + ch0 * 8] = ra0;
            *(uint4*)&sA[nxt][rA1 * PITCH + ch1 * 8] = ra1;
            *(uint4*)&sB[nxt][rA0 * PITCH + ch0 * 8] = rb0;
            *(uint4*)&sB[nxt][rA1 * PITCH + ch1 * 8] = rb1;
            __syncthreads();
        }
    }

    #pragma unroll
    for (int mi = 0; mi < 2; mi++) {
        int r0 = bm + wm + mi * 16 + g;
        int r1 = r0 + 8;
        #pragma unroll
        for (int nj = 0; nj < 4; nj++) {
            int col = wn + nj * 8 + 2 * tq;
            float bb0 = b1[col] + b2[col];
            float bb1 = b1[col + 1] + b2[col + 1];
            float4 d = acc[mi][nj];
            if (r0 < M) {
                float vx = d.x + bb0, vy = d.y + bb1;
                if (res) { vx += res[(size_t)r0 * 64 + col]; vy += res[(size_t)r0 * 64 + col + 1]; }
                *(float2*)&out[(size_t)r0 * 64 + col] = make_float2(vx, vy);
            }
            if (r1 < M) {
                float vx = d.z + bb0, vy = d.w + bb1;
                if (res) { vx += res[(size_t)r1 * 64 + col]; vy += res[(size_t)r1 * 64 + col + 1]; }
                *(float2*)&out[(size_t)r1 * 64 + col] = make_float2(vx, vy);
            }
        }
    }
}

// ---------------------------------------------------------------------------
// Small-O GEMM, fp16 A, transposed padded W cache [O][K+1].
// ---------------------------------------------------------------------------
template <int O>
__global__ void gemm_small(const __half* __restrict__ A, int lda, int M,
                           int K1, const float* __restrict__ W1,
                           int K2, const float* __restrict__ W2,
                           const float* __restrict__ bias1, const float* __restrict__ bias2,
                           float* __restrict__ out, int ldo, int ooff, float scale) {
    extern __shared__ float sW[];   // O * (K+1), transposed
    int tid = threadIdx.x;
    int K = K1 + K2;
    int KP = K + 1;
    for (int q = tid; q < K1 * O; q += blockDim.x) {
        int k = q / O, o = q - k * O;
        sW[o * KP + k] = W1[q];
    }
    for (int q = tid; q < K2 * O; q += blockDim.x) {
        int k = q / O, o = q - k * O;
        sW[o * KP + K1 + k] = W2[q];
    }
    __syncthreads();

    int warp = blockIdx.x * (blockDim.x >> 5) + (tid >> 5);
    int lane = tid & 31;
    if (warp >= M) return;
    const __half* Ar = A + (size_t)warp * lda;

    float acc[O];
    #pragma unroll
    for (int o = 0; o < O; o++) acc[o] = 0.f;

    for (int k = lane * 2; k < K; k += 64) {
        float2 a = __half22float2(*(const __half2*)(Ar + k));
        #pragma unroll
        for (int o = 0; o < O; o++)
            acc[o] += a.x * sW[o * KP + k] + a.y * sW[o * KP + k + 1];
    }

    float myv = 0.f;
    #pragma unroll
    for (int o = 0; o < O; o++) {
        float v = acc[o];
        v += __shfl_xor_sync(0xffffffffu, v, 16);
        v += __shfl_xor_sync(0xffffffffu, v, 8);
        v += __shfl_xor_sync(0xffffffffu, v, 4);
        v += __shfl_xor_sync(0xffffffffu, v, 2);
        v += __shfl_xor_sync(0xffffffffu, v, 1);
        if (lane == o) myv = v;
    }
    if (lane < O) {
        float r = myv + (bias1 ? bias1[lane] : 0.f) + (bias2 ? bias2[lane] : 0.f);
        out[(size_t)warp * ldo + ooff + lane] = r * scale;
    }
}

// ---------------------------------------------------------------------------
// Host launch
// ---------------------------------------------------------------------------
template <typename T>
static T* symaddr(const void* sym) {
    void* p = nullptr;
    cudaGetSymbolAddress(&p, sym);
    return (T*)p;
}

extern "C" void kernel_launch(void* const* d_in, const int* in_sizes, int n_in,
                              void* d_out, int out_size) {
    cudaFuncSetAttribute(scatter_split<4, 32, 0>, cudaFuncAttributeMaxDynamicSharedMemorySize, 64 * 1024);
    cudaFuncSetAttribute(scatter_split<3, 32, 0>, cudaFuncAttributeMaxDynamicSharedMemorySize, 64 * 1024);
    cudaFuncSetAttribute(gemm_small<3>, cudaFuncAttributeMaxDynamicSharedMemorySize, 64 * 1024);
    cudaFuncSetAttribute(gemm_small<32>, cudaFuncAttributeMaxDynamicSharedMemorySize, 64 * 1024);

    const float* pos       = (const float*)d_in[0];
    const float* vel       = (const float*)d_in[1];
    const float* box       = (const float*)d_in[2];
    const float* box_feats = (const float*)d_in[3];
    const float* cf_w = (const float*)d_in[4];
    const float* cf_b = (const float*)d_in[5];
    const float* co_w = (const float*)d_in[6];
    const float* co_b = (const float*)d_in[7];
    const float* d0_w = (const float*)d_in[8];
    const float* d0_b = (const float*)d_in[9];
    const float* c1_w = (const float*)d_in[10];
    const float* c1_b = (const float*)d_in[11];
    const float* d1_w = (const float*)d_in[12];
    const float* d1_b = (const float*)d_in[13];
    const float* c2_w = (const float*)d_in[14];
    const float* c2_b = (const float*)d_in[15];
    const float* d2_w = (const float*)d_in[16];
    const float* d2_b = (const float*)d_in[17];
    const float* c3_w = (const float*)d_in[18];
    const float* c3_b = (const float*)d_in[19];
    const float* d3_w = (const float*)d_in[20];
    const float* d3_b = (const float*)d_in[21];
    float* out = (float*)d_out;

    __half* S   = symaddr<__half>(g_S);
    float* x96  = symaddr<float>(g_x96);
    float* ya   = symaddr<float>(g_ya);
    float* yb   = symaddr<float>(g_yb);
    float* ff   = symaddr<float>(g_ff);
    __half* Wt1 = symaddr<__half>(g_Wt1);
    __half* Wt2 = symaddr<__half>(g_Wt2);
    int*   fcnt  = symaddr<int>(g_fcnt);
    int*   fidx  = symaddr<int>(g_fidx);
    int*   fcell = symaddr<int>(g_fcell);
    float* fcoef = symaddr<float>(g_fcoef);
    int*   ocnt  = symaddr<int>(g_ocnt);
    int*   oidx  = symaddr<int>(g_oidx);
    int*   ocell = symaddr<int>(g_ocell);
    float* ocoef = symaddr<float>(g_ocoef);

    const int M = NQ;

    // 0-2) hash grids
    dim3 gh((NQ + 255) / 256, 2);
    grid_hist2<<<gh, 256>>>(pos, box);                          // idx 0
    grid_scan2<<<2, NCELLS>>>();                                // idx 1
    grid_fill2<<<gh, 256>>>(pos, box);                          // idx 2

    // 3) neighbor search (ncu profiled slot)
    dim3 gn(NQ, 2);
    nbr_grid2<<<gn, 128>>>(pos, box);                           // idx 3

    // 4-5) weight convert + prep (independent)
    convertW<<<(K1TOT + K2TOT) / 32, 256>>>(c1_w, d1_w, c2_w, d2_w);
    prep_kernel<<<(NQ + 255) / 256, 256>>>(vel, d0_w, d0_b);

    // 6) first block: x96 = [a_co | a_cf | a_d0]  (scalar scatters, fp32 accum)
    scatter_split<4, 32, 0><<<NQ, 128, 32 * 64 * 4 * 4>>>(fcnt, fidx, fcell, fcoef, ff, 0, S, 256);
    gemm_small<32><<<(M + 7) / 8, 256, 257 * 32 * 4>>>(S, 256, M, 256, cf_w, 0, nullptr, cf_b, nullptr, x96, 96, 32, 1.f);
    scatter_split<3, 32, 0><<<NQ, 96, 32 * 64 * 3 * 4>>>(ocnt, oidx, ocell, ocoef, box_feats, 0, S, 192);
    gemm_small<32><<<(M + 7) / 8, 256, 193 * 32 * 4>>>(S, 192, M, 192, co_w, 0, nullptr, co_b, nullptr, x96, 96, 0, 1.f);

    dim3 gg((M + 63) / 64);

    // 7) layer 1: ya = S1 @ [c1_w; d1_w] + c1_b + d1_b   (tensor-core scatter + GEMM)
    scatter_mma<96><<<NQ, 128>>>(fcnt, fidx, fcell, fcoef, x96, S, K1TOT);
    gemm_hmma<<<gg, 128>>>(S, M, K1TOT, Wt1, c1_b, d1_b, nullptr, ya);

    // 8) layer 2: yb = S2 @ [c2_w; d2_w] + c2_b + d2_b + ya
    scatter_mma<64><<<NQ, 128>>>(fcnt, fidx, fcell, fcoef, ya, S, K2TOT);
    gemm_hmma<<<gg, 128>>>(S, M, K2TOT, Wt2, c2_b, d2_b, ya, yb);

    // 9) layer 3: out = (S3 @ [c3_w; d3_w] + c3_b + d3_b) / 128
    scatter_mma<64><<<NQ, 128>>>(fcnt, fidx, fcell, fcoef, yb, S, K2TOT);
    gemm_small<3><<<(M + 7) / 8, 256, 4161 * 3 * 4>>>(S, K2TOT, M, 4096, c3_w, 64, d3_w, c3_b, d3_b, out, 3, 0, 1.0f / 128.0f);
}

// round 13
// speedup vs baseline: 2.4837x; 1.3928x over previous
#include <cuda_runtime.h>
#include <cuda_bf16.h>
#include <cuda_fp16.h>
#include <math.h>

// ---------------------------------------------------------------------------
// Problem constants
// ---------------------------------------------------------------------------
#define NQ      6000
#define NBOX    3000
#define KMAX    80
#define CAP     256
#define KS      4
#define NCELL   64
#define RADIUS  0.1125f

#define GDIM    8
#define NCELLS  (GDIM*GDIM*GDIM)

#define K1TOT   6240     // layer1 GEMM K (6144 conv + 96 dense)
#define K2TOT   4160     // layer2 GEMM K (4096 conv + 64 dense)
#define SPLITK  4

// ---------------------------------------------------------------------------
// Device scratch
// ---------------------------------------------------------------------------
__device__ __align__(16) __half g_S[(size_t)NQ * K1TOT];
__device__ __align__(16) float g_x96[NQ * 96];
__device__ __align__(16) float g_ya[NQ * 64];
__device__ __align__(16) float g_yb[NQ * 64];
__device__ __align__(16) float g_ff[NQ * 4];
__device__ __align__(16) float g_part[SPLITK * NQ * 64];
__device__ __align__(16) __half g_Wt1[64 * K1TOT];   // [n][k] fp16, layer1
__device__ __align__(16) __half g_Wt2[64 * K2TOT];   // [n][k] fp16, layer2

__device__ int   g_fcnt[NQ];
__device__ int   g_fidx[NQ * KMAX];
__device__ int   g_fcell[NQ * KMAX];
__device__ __align__(16) float g_fcoef[(size_t)NQ * KMAX * 8];

__device__ int   g_ocnt[NQ];
__device__ int   g_oidx[NQ * KMAX];
__device__ int   g_ocell[NQ * KMAX];
__device__ __align__(16) float g_ocoef[(size_t)NQ * KMAX * 8];

// hash grids (0 = fluid/pos, 1 = box); counters self-re-zeroed in grid_scan2
__device__ int g_gcnt[2][NCELLS];
__device__ int g_gstart[2][NCELLS + 1];
__device__ int g_gcur[2][NCELLS];
__device__ int g_glistF[NQ];
__device__ int g_glistB[NBOX];

// ---------------------------------------------------------------------------
// Helpers
// ---------------------------------------------------------------------------
__device__ __forceinline__ float fsign(float x) {
    return (x > 0.f) ? 1.f : ((x < 0.f) ? -1.f : 0.f);
}

__device__ __forceinline__ int cell_coord(float x) {
    int c = (int)(x * (float)GDIM);
    return min(max(c, 0), GDIM - 1);
}

__device__ __forceinline__ void mma16816(float4& d, unsigned a0, unsigned a1,
                                         unsigned a2, unsigned a3,
                                         unsigned b0, unsigned b1) {
    asm volatile(
        "mma.sync.aligned.m16n8k16.row.col.f32.f16.f16.f32 "
        "{%0,%1,%2,%3}, {%4,%5,%6,%7}, {%8,%9}, {%0,%1,%2,%3};"
        : "+f"(d.x), "+f"(d.y), "+f"(d.z), "+f"(d.w)
        : "r"(a0), "r"(a1), "r"(a2), "r"(a3), "r"(b0), "r"(b1));
}

// ---------------------------------------------------------------------------
// Hash grid build
// ---------------------------------------------------------------------------
__global__ void grid_hist2(const float* __restrict__ pos, const float* __restrict__ box) {
    int g = blockIdx.y;
    const float* p = g ? box : pos;
    int n = g ? NBOX : NQ;
    int i = blockIdx.x * blockDim.x + threadIdx.x;
    if (i >= n) return;
    int cx = cell_coord(p[3 * i + 0]);
    int cy = cell_coord(p[3 * i + 1]);
    int cz = cell_coord(p[3 * i + 2]);
    atomicAdd(&g_gcnt[g][(cz * GDIM + cy) * GDIM + cx], 1);
}

__global__ void grid_scan2() {
    int g = blockIdx.x;
    __shared__ int s[NCELLS];
    int t = threadIdx.x;
    int v = g_gcnt[g][t];
    g_gcnt[g][t] = 0;          // reset for next replay (deterministic)
    s[t] = v;
    __syncthreads();
    for (int off = 1; off < NCELLS; off <<= 1) {
        int x = (t >= off) ? s[t - off] : 0;
        __syncthreads();
        s[t] += x;
        __syncthreads();
    }
    g_gstart[g][t + 1] = s[t];
    g_gcur[g][t] = s[t] - v;
    if (t == 0) g_gstart[g][0] = 0;
}

__global__ void grid_fill2(const float* __restrict__ pos, const float* __restrict__ box) {
    int g = blockIdx.y;
    const float* p = g ? box : pos;
    int n = g ? NBOX : NQ;
    int* list = g ? g_glistB : g_glistF;
    int i = blockIdx.x * blockDim.x + threadIdx.x;
    if (i >= n) return;
    int cx = cell_coord(p[3 * i + 0]);
    int cy = cell_coord(p[3 * i + 1]);
    int cz = cell_coord(p[3 * i + 2]);
    int slot = atomicAdd(&g_gcur[g][(cz * GDIM + cy) * GDIM + cx], 1);
    list[slot] = i;
}

// ---------------------------------------------------------------------------
// Neighbor search (both passes in one launch)
// ---------------------------------------------------------------------------
__global__ void nbr_grid2(const float* __restrict__ pos, const float* __restrict__ box) {
    int pass = blockIdx.y;
    const float* pin   = pass ? box : pos;
    const int*  glist  = pass ? g_glistB : g_glistF;
    const int*  gstart = g_gstart[pass];
    int selfExcl = pass ? 0 : 1;
    int* cnt_out  = pass ? g_ocnt  : g_fcnt;
    int* idx_out  = pass ? g_oidx  : g_fidx;
    int* cell_out = pass ? g_ocell : g_fcell;
    float* coef_out = pass ? g_ocoef : g_fcoef;

    int i = blockIdx.x;
    __shared__ float sd2[CAP];
    __shared__ int   sj[CAP];
    __shared__ int   ssel[KMAX];
    __shared__ int   scnt, skeep;
    int tid = threadIdx.x;
    if (tid == 0) { scnt = 0; skeep = 0; }
    __syncthreads();

    float qx = pos[3 * i + 0], qy = pos[3 * i + 1], qz = pos[3 * i + 2];
    const float R2 = RADIUS * RADIUS;

    int cx = cell_coord(qx), cy = cell_coord(qy), cz = cell_coord(qz);
    int x0 = max(cx - 1, 0), x1 = min(cx + 1, GDIM - 1);
    int y0 = max(cy - 1, 0), y1 = min(cy + 1, GDIM - 1);
    int z0 = max(cz - 1, 0), z1 = min(cz + 1, GDIM - 1);

    for (int z = z0; z <= z1; z++) {
        for (int y = y0; y <= y1; y++) {
            int cbase = (z * GDIM + y) * GDIM;
            int b = gstart[cbase + x0];
            int e = gstart[cbase + x1 + 1];
            for (int t = b + tid; t < e; t += blockDim.x) {
                int j = glist[t];
                if (selfExcl && j == i) continue;
                float dx = pin[3 * j + 0] - qx;
                float dy = pin[3 * j + 1] - qy;
                float dz = pin[3 * j + 2] - qz;
                float d2 = dx * dx + dy * dy + dz * dz;
                if (d2 <= R2) {
                    int p = atomicAdd(&scnt, 1);
                    if (p < CAP) { sd2[p] = d2; sj[p] = j; }
                }
            }
        }
    }
    __syncthreads();

    int cnt = min(scnt, CAP);
    int kcnt;
    if (cnt <= KMAX) {
        kcnt = cnt;
        for (int e = tid; e < cnt; e += blockDim.x) ssel[e] = sj[e];
    } else {
        kcnt = KMAX;
        for (int e = tid; e < cnt; e += blockDim.x) {
            float m2 = sd2[e]; int mj = sj[e]; int rank = 0;
            for (int q = 0; q < cnt; q++) {
                float o2 = sd2[q];
                rank += (o2 < m2) || (o2 == m2 && sj[q] < mj);
            }
            if (rank < KMAX) { int p = atomicAdd(&skeep, 1); ssel[p] = mj; }
        }
    }
    __syncthreads();
    if (tid == 0) cnt_out[i] = kcnt;

    const float EPS = 1e-12f;
    const float FP  = (float)(4.0 / 3.14159265358979323846);

    for (int k = tid; k < kcnt; k += blockDim.x) {
        int j = ssel[k];
        float rx = (pin[3 * j + 0] - qx) / RADIUS;
        float ry = (pin[3 * j + 1] - qy) / RADIUS;
        float rz = (pin[3 * j + 2] - qz) / RADIUS;

        float sq = rx * rx + ry * ry + rz * rz;
        float p1m = 1.0f - sq;
        float win = p1m * p1m * p1m;
        win = fminf(fmaxf(win, 0.f), 1.f);

        float nrm  = sqrtf(sq);
        float rxy2 = rx * rx + ry * ry;
        bool  polar = (1.25f * rz * rz) > rxy2;
        float s_pol = sqrtf(3.0f * nrm / (nrm + fabsf(rz) + EPS));
        float s_eq  = nrm / sqrtf(rxy2 + EPS);
        float xc = polar ? s_pol * rx : s_eq * rx;
        float yc = polar ? s_pol * ry : s_eq * ry;
        float zc = polar ? fsign(rz) * nrm : 1.5f * rz * s_eq;
        if (sq < 1e-12f) { xc = 0.f; yc = 0.f; zc = 0.f; }

        float rxy = sqrtf(xc * xc + yc * yc);
        float sx = (fabsf(xc) < EPS) ? EPS : xc;
        float sy = (fabsf(yc) < EPS) ? EPS : yc;
        float u1 = fsign(xc) * rxy;
        float v1 = u1 * FP * atanf(yc / sx);
        float v2 = fsign(yc) * rxy;
        float u2 = v2 * FP * atanf(xc / sy);
        float u, v;
        if (fabsf(xc) >= fabsf(yc)) { u = u1; v = v1; } else { u = u2; v = v2; }
        if (rxy < EPS) { u = 0.f; v = 0.f; }

        float gx = fminf(fmaxf((u  + 1.0f) * 0.5f * (float)(KS - 1), 0.f), (float)(KS - 1));
        float gy = fminf(fmaxf((v  + 1.0f) * 0.5f * (float)(KS - 1), 0.f), (float)(KS - 1));
        float gz = fminf(fmaxf((zc + 1.0f) * 0.5f * (float)(KS - 1), 0.f), (float)(KS - 1));
        int ix = min((int)floorf(gx), KS - 2);
        int iy = min((int)floorf(gy), KS - 2);
        int iz = min((int)floorf(gz), KS - 2);
        float tx = gx - (float)ix, ty = gy - (float)iy, tz = gz - (float)iz;

        int slot = i * KMAX + k;
        idx_out[slot]  = j;
        cell_out[slot] = (iz * KS + iy) * KS + ix;

        float wx[2] = {1.f - tx, tx};
        float wy[2] = {1.f - ty, ty};
        float wz[2] = {1.f - tz, tz};
        float* cf = coef_out + (size_t)slot * 8;
        #pragma unroll
        for (int dx = 0; dx < 2; dx++)
            #pragma unroll
            for (int dy = 0; dy < 2; dy++)
                #pragma unroll
                for (int dz = 0; dz < 2; dz++)
                    cf[dx * 4 + dy * 2 + dz] = wx[dx] * wy[dy] * wz[dz] * win;
    }
}

// ---------------------------------------------------------------------------
// convertW: build fp16 transposed weights Wt[n][k] for both HMMA layers.
// ---------------------------------------------------------------------------
__global__ void convertW(const float* __restrict__ c1w, const float* __restrict__ d1w,
                         const float* __restrict__ c2w, const float* __restrict__ d2w) {
    __shared__ float s[32][65];
    int t = blockIdx.x;
    const float *Wa, *Wb;
    __half* Wt;
    int K, Ka, k0;
    if (t < K1TOT / 32) {
        k0 = t * 32; K = K1TOT; Ka = 6144; Wa = c1w; Wb = d1w; Wt = g_Wt1;
    } else {
        k0 = (t - K1TOT / 32) * 32; K = K2TOT; Ka = 4096; Wa = c2w; Wb = d2w; Wt = g_Wt2;
    }
    int tid = threadIdx.x;
    #pragma unroll
    for (int i = 0; i < 8; i++) {
        int idx = tid + i * 256;          // 0..2047
        int row = idx >> 6;               // k offset 0..31
        int col = idx & 63;               // n
        int k = k0 + row;
        float v = (k < Ka) ? Wa[(size_t)k * 64 + col] : Wb[(size_t)(k - Ka) * 64 + col];
        s[row][col] = v;
    }
    __syncthreads();
    #pragma unroll
    for (int i = 0; i < 8; i++) {
        int idx = tid + i * 256;
        int n  = idx >> 5;                // 0..63
        int kk = idx & 31;
        Wt[(size_t)n * K + k0 + kk] = __float2half_rn(s[kk][n]);
    }
}

// ---------------------------------------------------------------------------
// prep: ff = [1,vel]; x96[:,64:96] = ff @ d0_w + d0_b
// ---------------------------------------------------------------------------
__global__ void prep_kernel(const float* __restrict__ vel,
                            const float* __restrict__ d0_w, const float* __restrict__ d0_b) {
    int i = blockIdx.x * blockDim.x + threadIdx.x;
    if (i >= NQ) return;
    float f1 = vel[i * 3 + 0], f2 = vel[i * 3 + 1], f3 = vel[i * 3 + 2];
    g_ff[i * 4 + 0] = 1.0f;
    g_ff[i * 4 + 1] = f1;
    g_ff[i * 4 + 2] = f2;
    g_ff[i * 4 + 3] = f3;
    #pragma unroll 8
    for (int o = 0; o < 32; o++) {
        g_x96[i * 96 + 64 + o] = d0_w[o] + f1 * d0_w[32 + o] + f2 * d0_w[64 + o]
                                 + f3 * d0_w[96 + o] + d0_b[o];
    }
}

// ---------------------------------------------------------------------------
// Merged first-block scatter: y=0 fluid/ff (F=4, ldS=256, dst S0),
//                             y=1 box/box_feats (F=3, ldS=192, dst S1).
// fp32 smem accumulation (32-way k-split), fp16 writeout, no relu.
// ---------------------------------------------------------------------------
__global__ void scatter_first(const float* __restrict__ box_feats) {
    int pass = blockIdx.y;
    const int F = pass ? 3 : 4;
    const int nF = 64 * F;
    const float* feats = pass ? box_feats : g_ff;
    const int* cnt  = pass ? g_ocnt  : g_fcnt;
    const int* nidx = pass ? g_oidx  : g_fidx;
    const int* ncel = pass ? g_ocell : g_fcell;
    const float* ncoef = pass ? g_ocoef : g_fcoef;
    __half* dst = g_S + (pass ? (size_t)NQ * 256 : 0);
    int ldS = pass ? 192 : 256;

    int i = blockIdx.x;
    extern __shared__ float shS[];            // 32 * nF floats (<= 32KB)
    __shared__ float shC[KMAX * 8];
    __shared__ int   shI[KMAX];
    __shared__ int   shCe[KMAX];
    int tid = threadIdx.x;
    const int NT = 128;

    for (int q = tid; q < 32 * nF; q += NT) shS[q] = 0.f;
    int c = cnt[i];
    for (int q = tid; q < c; q += NT) {
        shI[q]  = nidx[i * KMAX + q];
        shCe[q] = ncel[i * KMAX + q];
    }
    for (int q = tid; q < c * 8; q += NT)
        shC[q] = ncoef[(size_t)i * KMAX * 8 + q];
    __syncthreads();

    {
        int f = tid % F;
        int s = tid / F;
        if (s < 32) {
            int k0 = (c * s) / 32;
            int k1 = (c * (s + 1)) / 32;
            float* my = shS + s * nF;
            const int OFF[8] = {0, 16, 4, 20, 1, 17, 5, 21};
            for (int k = k0; k < k1; k++) {
                int j = shI[k];
                float vv = feats[(size_t)j * F + f];
                int base = shCe[k] * F + f;
                #pragma unroll
                for (int cc = 0; cc < 8; cc++)
                    my[base + OFF[cc] * F] += shC[k * 8 + cc] * vv;
            }
        }
    }
    __syncthreads();

    __half* drow = dst + (size_t)i * ldS;
    for (int q = tid * 2; q < nF; q += NT * 2) {
        float v0 = shS[q], v1 = shS[q + 1];
        #pragma unroll
        for (int s = 1; s < 32; s++) { v0 += shS[s * nF + q]; v1 += shS[s * nF + q + 1]; }
        *(__half2*)(drow + q) = __floats2half2_rn(v0, v1);
    }
}

// ---------------------------------------------------------------------------
// Merged 32-col GEMM pair: y=0 cf (K=256, S0, out cols 32..63),
//                          y=1 co (K=192, S1, out cols 0..31).
// W cached transposed [32][K+1] in shared. Writes into g_x96.
// ---------------------------------------------------------------------------
__global__ void gemm32_pair(const float* __restrict__ cf_w, const float* __restrict__ cf_b,
                            const float* __restrict__ co_w, const float* __restrict__ co_b) {
    int pass = blockIdx.y;
    int K = pass ? 192 : 256;
    const __half* A = g_S + (pass ? (size_t)NQ * 256 : 0);
    const float* W = pass ? co_w : cf_w;
    const float* b = pass ? co_b : cf_b;
    int ooff = pass ? 0 : 32;

    extern __shared__ float sW[];   // 32 * (K+1)
    int tid = threadIdx.x;
    int KP = K + 1;
    for (int q = tid; q < K * 32; q += blockDim.x) {
        int k = q >> 5, o = q & 31;
        sW[o * KP + k] = W[q];
    }
    __syncthreads();

    int warp = blockIdx.x * 8 + (tid >> 5);
    int lane = tid & 31;
    if (warp >= NQ) return;
    const __half* Ar = A + (size_t)warp * K;

    float acc[32];
    #pragma unroll
    for (int o = 0; o < 32; o++) acc[o] = 0.f;

    for (int k = lane * 2; k < K; k += 64) {
        float2 a = __half22float2(*(const __half2*)(Ar + k));
        #pragma unroll
        for (int o = 0; o < 32; o++)
            acc[o] += a.x * sW[o * KP + k] + a.y * sW[o * KP + k + 1];
    }

    float myv = 0.f;
    #pragma unroll
    for (int o = 0; o < 32; o++) {
        float v = acc[o];
        v += __shfl_xor_sync(0xffffffffu, v, 16);
        v += __shfl_xor_sync(0xffffffffu, v, 8);
        v += __shfl_xor_sync(0xffffffffu, v, 4);
        v += __shfl_xor_sync(0xffffffffu, v, 2);
        v += __shfl_xor_sync(0xffffffffu, v, 1);
        if (lane == o) myv = v;
    }
    g_x96[(size_t)warp * 96 + ooff + lane] = myv + b[lane];
}

// ---------------------------------------------------------------------------
// Tensor-core scatter: S_row[64,F] = CoefDense[64,80] @ NF[80,F] per particle.
// ---------------------------------------------------------------------------
#define PA 82   // smem pitch in halves

template <int F>
__global__ void scatter_mma(const int* __restrict__ cnt, const int* __restrict__ nidx,
                            const int* __restrict__ ncell, const float* __restrict__ ncoef,
                            const float* __restrict__ feats,
                            __half* __restrict__ Sout, int ldS) {
    __shared__ __half sA[64 * PA];      // coef dense [cell][k]
    __shared__ __half sB[F * PA];       // feats transposed [f][k]
    __shared__ float shC[KMAX * 8];
    __shared__ int   shI[KMAX];

    int i = blockIdx.x;
    int tid = threadIdx.x;
    int warp = tid >> 5, lane = tid & 31;
    int g = lane >> 2, tq = lane & 3;

    unsigned* za = (unsigned*)sA;
    unsigned* zb = (unsigned*)sB;
    for (int q = tid; q < 64 * PA / 2; q += 128) za[q] = 0u;
    for (int q = tid; q < F * PA / 2; q += 128) zb[q] = 0u;

    int c = cnt[i];
    for (int q = tid; q < c; q += 128) shI[q] = nidx[i * KMAX + q];
    for (int q = tid; q < c * 8; q += 128) shC[q] = ncoef[(size_t)i * KMAX * 8 + q];
    __syncthreads();

    {
        const int OFF[8] = {0, 16, 4, 20, 1, 17, 5, 21};
        __shared__ int shCe[KMAX];
        for (int q = tid; q < c; q += 128) shCe[q] = ncell[i * KMAX + q];
        __syncthreads();
        for (int t = tid; t < c * 8; t += 128) {
            int k = t >> 3, cc = t & 7;
            sA[(shCe[k] + OFF[cc]) * PA + k] = __float2half_rn(shC[t]);
        }
    }

    for (int k = warp; k < c; k += 4) {
        const float* fr = feats + (size_t)shI[k] * F;
        #pragma unroll
        for (int f = lane; f < F; f += 32)
            sB[f * PA + k] = __float2half_rn(fmaxf(fr[f], 0.f));
    }
    __syncthreads();

    float4 acc[F / 8];
    #pragma unroll
    for (int nj = 0; nj < F / 8; nj++) acc[nj] = make_float4(0.f, 0.f, 0.f, 0.f);

    #pragma unroll
    for (int ks = 0; ks < KMAX; ks += 16) {
        int rbase = (warp * 16 + g) * PA + ks + 2 * tq;
        unsigned a0 = *(const unsigned*)&sA[rbase];
        unsigned a1 = *(const unsigned*)&sA[rbase + 8 * PA];
        unsigned a2 = *(const unsigned*)&sA[rbase + 8];
        unsigned a3 = *(const unsigned*)&sA[rbase + 8 * PA + 8];
        #pragma unroll
        for (int nj = 0; nj < F / 8; nj++) {
            int nbase = (nj * 8 + g) * PA + ks + 2 * tq;
            unsigned b0 = *(const unsigned*)&sB[nbase];
            unsigned b1 = *(const unsigned*)&sB[nbase + 8];
            mma16816(acc[nj], a0, a1, a2, a3, b0, b1);
        }
    }

    __half* dst = Sout + (size_t)i * ldS;
    int r0 = warp * 16 + g, r1 = r0 + 8;
    #pragma unroll
    for (int nj = 0; nj < F / 8; nj++) {
        int col = nj * 8 + 2 * tq;
        *(__half2*)(dst + r0 * F + col) = __floats2half2_rn(acc[nj].x, acc[nj].y);
        *(__half2*)(dst + r1 * F + col) = __floats2half2_rn(acc[nj].z, acc[nj].w);
    }
    if (tid < F)
        dst[64 * F + tid] = __float2half_rn(fmaxf(feats[(size_t)i * F + tid], 0.f));
}

// ---------------------------------------------------------------------------
// HMMA GEMM with split-K: grid (ceil(M/64), SPLITK). Each split writes a raw
// partial [M,64] fp32 to part + y*M*64 (no bias/res; combine4 finishes).
// ---------------------------------------------------------------------------
#define PITCH 40

__global__ void gemm_hmma_sk(const __half* __restrict__ A, int M, int K,
                             const __half* __restrict__ Wt,
                             float* __restrict__ part) {
    __shared__ __half sA[2][64 * PITCH];
    __shared__ __half sB[2][64 * PITCH];

    int tid = threadIdx.x;
    int warp = tid >> 5, lane = tid & 31;
    int g = lane >> 2, tq = lane & 3;
    int wm = (warp & 1) * 32, wn = (warp >> 1) * 32;
    int bm = blockIdx.x * 64;

    int nt = K / 32;
    int tps = (nt + SPLITK - 1) / SPLITK;
    int t0 = blockIdx.y * tps;
    int t1 = min(t0 + tps, nt);
    float* out = part + (size_t)blockIdx.y * M * 64;

    int c0 = tid * 2, c1 = c0 + 1;
    int rA0 = c0 >> 2, ch0 = c0 & 3;
    int rA1 = c1 >> 2, ch1 = c1 & 3;
    bool ok0 = (bm + rA0) < M, ok1 = (bm + rA1) < M;
    const __half* Ab0 = A + (size_t)(bm + rA0) * K + ch0 * 8;
    const __half* Ab1 = A + (size_t)(bm + rA1) * K + ch1 * 8;
    const __half* Wb0 = Wt + (size_t)rA0 * K + ch0 * 8;
    const __half* Wb1 = Wt + (size_t)rA1 * K + ch1 * 8;

    float4 acc[2][4];
    #pragma unroll
    for (int i = 0; i < 2; i++)
        #pragma unroll
        for (int j = 0; j < 4; j++) acc[i][j] = make_float4(0.f, 0.f, 0.f, 0.f);

    const uint4 Z = make_uint4(0u, 0u, 0u, 0u);
    uint4 ra0, ra1, rb0, rb1;

    {
        int kt = t0 * 32;
        ra0 = ok0 ? *(const uint4*)(Ab0 + kt) : Z;
        ra1 = ok1 ? *(const uint4*)(Ab1 + kt) : Z;
        rb0 = *(const uint4*)(Wb0 + kt);
        rb1 = *(const uint4*)(Wb1 + kt);
    }
    *(uint4*)&sA[0][rA0 * PITCH + ch0 * 8] = ra0;
    *(uint4*)&sA[0][rA1 * PITCH + ch1 * 8] = ra1;
    *(uint4*)&sB[0][rA0 * PITCH + ch0 * 8] = rb0;
    *(uint4*)&sB[0][rA1 * PITCH + ch1 * 8] = rb1;
    __syncthreads();

    for (int t = t0; t < t1; t++) {
        int cur = (t - t0) & 1;
        if (t + 1 < t1) {
            int kt = (t + 1) * 32;
            ra0 = ok0 ? *(const uint4*)(Ab0 + kt) : Z;
            ra1 = ok1 ? *(const uint4*)(Ab1 + kt) : Z;
            rb0 = *(const uint4*)(Wb0 + kt);
            rb1 = *(const uint4*)(Wb1 + kt);
        }

        const __half* cA = sA[cur];
        const __half* cB = sB[cur];
        #pragma unroll
        for (int ks = 0; ks < 32; ks += 16) {
            unsigned af[2][4], bf[4][2];
            #pragma unroll
            for (int mi = 0; mi < 2; mi++) {
                int rbase = (wm + mi * 16 + g) * PITCH + ks + 2 * tq;
                af[mi][0] = *(const unsigned*)&cA[rbase];
                af[mi][1] = *(const unsigned*)&cA[rbase + 8 * PITCH];
                af[mi][2] = *(const unsigned*)&cA[rbase + 8];
                af[mi][3] = *(const unsigned*)&cA[rbase + 8 * PITCH + 8];
            }
            #pragma unroll
            for (int nj = 0; nj < 4; nj++) {
                int nbase = (wn + nj * 8 + g) * PITCH + ks + 2 * tq;
                bf[nj][0] = *(const unsigned*)&cB[nbase];
                bf[nj][1] = *(const unsigned*)&cB[nbase + 8];
            }
            #pragma unroll
            for (int mi = 0; mi < 2; mi++)
                #pragma unroll
                for (int nj = 0; nj < 4; nj++)
                    mma16816(acc[mi][nj], af[mi][0], af[mi][1], af[mi][2], af[mi][3],
                             bf[nj][0], bf[nj][1]);
        }

        if (t + 1 < t1) {
            int nxt = cur ^ 1;
            *(uint4*)&sA[nxt][rA0 * PITCH + ch0 * 8] = ra0;
            *(uint4*)&sA[nxt][rA1 * PITCH + ch1 * 8] = ra1;
            *(uint4*)&sB[nxt][rA0 * PITCH + ch0 * 8] = rb0;
            *(uint4*)&sB[nxt][rA1 * PITCH + ch1 * 8] = rb1;
            __syncthreads();
        }
    }

    #pragma unroll
    for (int mi = 0; mi < 2; mi++) {
        int r0 = bm + wm + mi * 16 + g;
        int r1 = r0 + 8;
        #pragma unroll
        for (int nj = 0; nj < 4; nj++) {
            int col = wn + nj * 8 + 2 * tq;
            float4 d = acc[mi][nj];
            if (r0 < M) *(float2*)&out[(size_t)r0 * 64 + col] = make_float2(d.x, d.y);
            if (r1 < M) *(float2*)&out[(size_t)r1 * 64 + col] = make_float2(d.z, d.w);
        }
    }
}

// ---------------------------------------------------------------------------
// combine4: out = sum(4 partials) + b1 + b2 (+ res)
// ---------------------------------------------------------------------------
__global__ void combine4(const float* __restrict__ part,
                         const float* __restrict__ b1, const float* __restrict__ b2,
                         const float* __restrict__ res, float* __restrict__ out, int M) {
    int idx = blockIdx.x * blockDim.x + threadIdx.x;
    if (idx >= M * 64) return;
    int c = idx & 63;
    size_t st = (size_t)M * 64;
    float v = part[idx] + part[st + idx] + part[2 * st + idx] + part[3 * st + idx]
              + b1[c] + b2[c];
    if (res) v += res[idx];
    out[idx] = v;
}

// ---------------------------------------------------------------------------
// Small-O GEMM (final layer), fp16 A, transposed padded W cache [O][K+1].
// ---------------------------------------------------------------------------
template <int O>
__global__ void gemm_small(const __half* __restrict__ A, int lda, int M,
                           int K1, const float* __restrict__ W1,
                           int K2, const float* __restrict__ W2,
                           const float* __restrict__ bias1, const float* __restrict__ bias2,
                           float* __restrict__ out, int ldo, int ooff, float scale) {
    extern __shared__ float sW[];   // O * (K+1), transposed
    int tid = threadIdx.x;
    int K = K1 + K2;
    int KP = K + 1;
    for (int q = tid; q < K1 * O; q += blockDim.x) {
        int k = q / O, o = q - k * O;
        sW[o * KP + k] = W1[q];
    }
    for (int q = tid; q < K2 * O; q += blockDim.x) {
        int k = q / O, o = q - k * O;
        sW[o * KP + K1 + k] = W2[q];
    }
    __syncthreads();

    int warp = blockIdx.x * (blockDim.x >> 5) + (tid >> 5);
    int lane = tid & 31;
    if (warp >= M) return;
    const __half* Ar = A + (size_t)warp * lda;

    float acc[O];
    #pragma unroll
    for (int o = 0; o < O; o++) acc[o] = 0.f;

    for (int k = lane * 2; k < K; k += 64) {
        float2 a = __half22float2(*(const __half2*)(Ar + k));
        #pragma unroll
        for (int o = 0; o < O; o++)
            acc[o] += a.x * sW[o * KP + k] + a.y * sW[o * KP + k + 1];
    }

    float myv = 0.f;
    #pragma unroll
    for (int o = 0; o < O; o++) {
        float v = acc[o];
        v += __shfl_xor_sync(0xffffffffu, v, 16);
        v += __shfl_xor_sync(0xffffffffu, v, 8);
        v += __shfl_xor_sync(0xffffffffu, v, 4);
        v += __shfl_xor_sync(0xffffffffu, v, 2);
        v += __shfl_xor_sync(0xffffffffu, v, 1);
        if (lane == o) myv = v;
    }
    if (lane < O) {
        float r = myv + (bias1 ? bias1[lane] : 0.f) + (bias2 ? bias2[lane] : 0.f);
        out[(size_t)warp * ldo + ooff + lane] = r * scale;
    }
}

// ---------------------------------------------------------------------------
// Host launch
// ---------------------------------------------------------------------------
template <typename T>
static T* symaddr(const void* sym) {
    void* p = nullptr;
    cudaGetSymbolAddress(&p, sym);
    return (T*)p;
}

extern "C" void kernel_launch(void* const* d_in, const int* in_sizes, int n_in,
                              void* d_out, int out_size) {
    cudaFuncSetAttribute(gemm_small<3>, cudaFuncAttributeMaxDynamicSharedMemorySize, 64 * 1024);

    const float* pos       = (const float*)d_in[0];
    const float* vel       = (const float*)d_in[1];
    const float* box       = (const float*)d_in[2];
    const float* box_feats = (const float*)d_in[3];
    const float* cf_w = (const float*)d_in[4];
    const float* cf_b = (const float*)d_in[5];
    const float* co_w = (const float*)d_in[6];
    const float* co_b = (const float*)d_in[7];
    const float* d0_w = (const float*)d_in[8];
    const float* d0_b = (const float*)d_in[9];
    const float* c1_w = (const float*)d_in[10];
    const float* c1_b = (const float*)d_in[11];
    const float* d1_w = (const float*)d_in[12];
    const float* d1_b = (const float*)d_in[13];
    const float* c2_w = (const float*)d_in[14];
    const float* c2_b = (const float*)d_in[15];
    const float* d2_w = (const float*)d_in[16];
    const float* d2_b = (const float*)d_in[17];
    const float* c3_w = (const float*)d_in[18];
    const float* c3_b = (const float*)d_in[19];
    const float* d3_w = (const float*)d_in[20];
    const float* d3_b = (const float*)d_in[21];
    float* out = (float*)d_out;

    __half* S   = symaddr<__half>(g_S);
    float* x96  = symaddr<float>(g_x96);
    float* ya   = symaddr<float>(g_ya);
    float* yb   = symaddr<float>(g_yb);
    float* part = symaddr<float>(g_part);
    __half* Wt1 = symaddr<__half>(g_Wt1);
    __half* Wt2 = symaddr<__half>(g_Wt2);
    int*   fcnt  = symaddr<int>(g_fcnt);
    int*   fidx  = symaddr<int>(g_fidx);
    int*   fcell = symaddr<int>(g_fcell);
    float* fcoef = symaddr<float>(g_fcoef);

    const int M = NQ;

    // 0-2) hash grids
    dim3 gh((NQ + 255) / 256, 2);
    grid_hist2<<<gh, 256>>>(pos, box);                          // idx 0
    grid_scan2<<<2, NCELLS>>>();                                // idx 1
    grid_fill2<<<gh, 256>>>(pos, box);                          // idx 2

    // 3) neighbor search (ncu profiled slot)
    dim3 gn(NQ, 2);
    nbr_grid2<<<gn, 128>>>(pos, box);                           // idx 3

    // 4-5) weight convert + prep (independent)
    convertW<<<(K1TOT + K2TOT) / 32, 256>>>(c1_w, d1_w, c2_w, d2_w);
    prep_kernel<<<(NQ + 255) / 256, 256>>>(vel, d0_w, d0_b);

    // 6-7) first block (merged): x96 = [a_co | a_cf | a_d0]
    dim3 gs(NQ, 2);
    scatter_first<<<gs, 128, 32 * 64 * 4 * 4>>>(box_feats);
    dim3 gp((M + 7) / 8, 2);
    gemm32_pair<<<gp, 256, 257 * 32 * 4>>>(cf_w, cf_b, co_w, co_b);

    dim3 gg((M + 63) / 64, SPLITK);

    // 8-10) layer 1: ya = S1 @ [c1_w; d1_w] + c1_b + d1_b
    scatter_mma<96><<<NQ, 128>>>(fcnt, fidx, fcell, fcoef, x96, S, K1TOT);
    gemm_hmma_sk<<<gg, 128>>>(S, M, K1TOT, Wt1, part);
    combine4<<<(M * 64 + 255) / 256, 256>>>(part, c1_b, d1_b, nullptr, ya, M);

    // 11-13) layer 2: yb = S2 @ [c2_w; d2_w] + c2_b + d2_b + ya
    scatter_mma<64><<<NQ, 128>>>(fcnt, fidx, fcell, fcoef, ya, S, K2TOT);
    gemm_hmma_sk<<<gg, 128>>>(S, M, K2TOT, Wt2, part);
    combine4<<<(M * 64 + 255) / 256, 256>>>(part, c2_b, d2_b, ya, yb, M);

    // 14-15) layer 3: out = (S3 @ [c3_w; d3_w] + c3_b + d3_b) / 128
    scatter_mma<64><<<NQ, 128>>>(fcnt, fidx, fcell, fcoef, yb, S, K2TOT);
    gemm_small<3><<<(M + 7) / 8, 256, 4161 * 3 * 4>>>(S, K2TOT, M, 4096, c3_w, 64, d3_w, c3_b, d3_b, out, 3, 0, 1.0f / 128.0f);
}

// round 15
// speedup vs baseline: 2.5657x; 1.0330x over previous
#include <cuda_runtime.h>
#include <cuda_bf16.h>
#include <cuda_fp16.h>
#include <math.h>

// ---------------------------------------------------------------------------
// Problem constants
// ---------------------------------------------------------------------------
#define NQ      6000
#define NBOX    3000
#define KMAX    80
#define CAP     256
#define KS      4
#define NCELL   64
#define RADIUS  0.1125f

#define GDIM    8
#define NCELLS  (GDIM*GDIM*GDIM)

#define K1TOT   6240     // layer1 GEMM K (6144 conv + 96 dense)
#define K2TOT   4160     // layer2 GEMM K (4096 conv + 64 dense)
#define SPLITK  4

// ---------------------------------------------------------------------------
// Device scratch
// ---------------------------------------------------------------------------
__device__ __align__(16) __half g_S[(size_t)NQ * K1TOT];
__device__ __align__(16) float g_x96[NQ * 96];
__device__ __align__(16) float g_ya[NQ * 64];
__device__ __align__(16) float g_yb[NQ * 64];
__device__ __align__(16) float g_ff[NQ * 4];
__device__ __align__(16) float g_part[SPLITK * NQ * 64];
__device__ __align__(16) __half g_Wt1[64 * K1TOT];   // [n][k] fp16, layer1
__device__ __align__(16) __half g_Wt2[64 * K2TOT];   // [n][k] fp16, layer2

__device__ int   g_fcnt[NQ];
__device__ int   g_fidx[NQ * KMAX];
__device__ int   g_fcell[NQ * KMAX];
__device__ __align__(16) float g_fcoef[(size_t)NQ * KMAX * 8];

__device__ int   g_ocnt[NQ];
__device__ int   g_oidx[NQ * KMAX];
__device__ int   g_ocell[NQ * KMAX];
__device__ __align__(16) float g_ocoef[(size_t)NQ * KMAX * 8];

// hash grids (0 = fluid/pos, 1 = box); counters self-re-zeroed in grid_scan2
__device__ int g_gcnt[2][NCELLS];
__device__ int g_gstart[2][NCELLS + 1];
__device__ int g_gcur[2][NCELLS];
__device__ int g_glistF[NQ];
__device__ int g_glistB[NBOX];

// ---------------------------------------------------------------------------
// Helpers
// ---------------------------------------------------------------------------
__device__ __forceinline__ float fsign(float x) {
    return (x > 0.f) ? 1.f : ((x < 0.f) ? -1.f : 0.f);
}

__device__ __forceinline__ int cell_coord(float x) {
    int c = (int)(x * (float)GDIM);
    return min(max(c, 0), GDIM - 1);
}

__device__ __forceinline__ void mma16816(float4& d, unsigned a0, unsigned a1,
                                         unsigned a2, unsigned a3,
                                         unsigned b0, unsigned b1) {
    asm volatile(
        "mma.sync.aligned.m16n8k16.row.col.f32.f16.f16.f32 "
        "{%0,%1,%2,%3}, {%4,%5,%6,%7}, {%8,%9}, {%0,%1,%2,%3};"
        : "+f"(d.x), "+f"(d.y), "+f"(d.z), "+f"(d.w)
        : "r"(a0), "r"(a1), "r"(a2), "r"(a3), "r"(b0), "r"(b1));
}

// ---------------------------------------------------------------------------
// Hash grid build
// ---------------------------------------------------------------------------
__global__ void grid_hist2(const float* __restrict__ pos, const float* __restrict__ box) {
    int g = blockIdx.y;
    const float* p = g ? box : pos;
    int n = g ? NBOX : NQ;
    int i = blockIdx.x * blockDim.x + threadIdx.x;
    if (i >= n) return;
    int cx = cell_coord(p[3 * i + 0]);
    int cy = cell_coord(p[3 * i + 1]);
    int cz = cell_coord(p[3 * i + 2]);
    atomicAdd(&g_gcnt[g][(cz * GDIM + cy) * GDIM + cx], 1);
}

__global__ void grid_scan2() {
    int g = blockIdx.x;
    __shared__ int s[NCELLS];
    int t = threadIdx.x;
    int v = g_gcnt[g][t];
    g_gcnt[g][t] = 0;          // reset for next replay (deterministic)
    s[t] = v;
    __syncthreads();
    for (int off = 1; off < NCELLS; off <<= 1) {
        int x = (t >= off) ? s[t - off] : 0;
        __syncthreads();
        s[t] += x;
        __syncthreads();
    }
    g_gstart[g][t + 1] = s[t];
    g_gcur[g][t] = s[t] - v;
    if (t == 0) g_gstart[g][0] = 0;
}

__global__ void grid_fill2(const float* __restrict__ pos, const float* __restrict__ box) {
    int g = blockIdx.y;
    const float* p = g ? box : pos;
    int n = g ? NBOX : NQ;
    int* list = g ? g_glistB : g_glistF;
    int i = blockIdx.x * blockDim.x + threadIdx.x;
    if (i >= n) return;
    int cx = cell_coord(p[3 * i + 0]);
    int cy = cell_coord(p[3 * i + 1]);
    int cz = cell_coord(p[3 * i + 2]);
    int slot = atomicAdd(&g_gcur[g][(cz * GDIM + cy) * GDIM + cx], 1);
    list[slot] = i;
}

// ---------------------------------------------------------------------------
// Neighbor search (both passes in one launch)
// ---------------------------------------------------------------------------
__global__ void nbr_grid2(const float* __restrict__ pos, const float* __restrict__ box) {
    int pass = blockIdx.y;
    const float* pin   = pass ? box : pos;
    const int*  glist  = pass ? g_glistB : g_glistF;
    const int*  gstart = g_gstart[pass];
    int selfExcl = pass ? 0 : 1;
    int* cnt_out  = pass ? g_ocnt  : g_fcnt;
    int* idx_out  = pass ? g_oidx  : g_fidx;
    int* cell_out = pass ? g_ocell : g_fcell;
    float* coef_out = pass ? g_ocoef : g_fcoef;

    int i = blockIdx.x;
    __shared__ float sd2[CAP];
    __shared__ int   sj[CAP];
    __shared__ int   ssel[KMAX];
    __shared__ int   scnt, skeep;
    int tid = threadIdx.x;
    if (tid == 0) { scnt = 0; skeep = 0; }
    __syncthreads();

    float qx = pos[3 * i + 0], qy = pos[3 * i + 1], qz = pos[3 * i + 2];
    const float R2 = RADIUS * RADIUS;

    int cx = cell_coord(qx), cy = cell_coord(qy), cz = cell_coord(qz);
    int x0 = max(cx - 1, 0), x1 = min(cx + 1, GDIM - 1);
    int y0 = max(cy - 1, 0), y1 = min(cy + 1, GDIM - 1);
    int z0 = max(cz - 1, 0), z1 = min(cz + 1, GDIM - 1);

    for (int z = z0; z <= z1; z++) {
        for (int y = y0; y <= y1; y++) {
            int cbase = (z * GDIM + y) * GDIM;
            int b = gstart[cbase + x0];
            int e = gstart[cbase + x1 + 1];
            for (int t = b + tid; t < e; t += blockDim.x) {
                int j = glist[t];
                if (selfExcl && j == i) continue;
                float dx = pin[3 * j + 0] - qx;
                float dy = pin[3 * j + 1] - qy;
                float dz = pin[3 * j + 2] - qz;
                float d2 = dx * dx + dy * dy + dz * dz;
                if (d2 <= R2) {
                    int p = atomicAdd(&scnt, 1);
                    if (p < CAP) { sd2[p] = d2; sj[p] = j; }
                }
            }
        }
    }
    __syncthreads();

    int cnt = min(scnt, CAP);
    int kcnt;
    if (cnt <= KMAX) {
        kcnt = cnt;
        for (int e = tid; e < cnt; e += blockDim.x) ssel[e] = sj[e];
    } else {
        kcnt = KMAX;
        for (int e = tid; e < cnt; e += blockDim.x) {
            float m2 = sd2[e]; int mj = sj[e]; int rank = 0;
            for (int q = 0; q < cnt; q++) {
                float o2 = sd2[q];
                rank += (o2 < m2) || (o2 == m2 && sj[q] < mj);
            }
            if (rank < KMAX) { int p = atomicAdd(&skeep, 1); ssel[p] = mj; }
        }
    }
    __syncthreads();
    if (tid == 0) cnt_out[i] = kcnt;

    const float EPS = 1e-12f;
    const float FP  = (float)(4.0 / 3.14159265358979323846);

    for (int k = tid; k < kcnt; k += blockDim.x) {
        int j = ssel[k];
        float rx = (pin[3 * j + 0] - qx) / RADIUS;
        float ry = (pin[3 * j + 1] - qy) / RADIUS;
        float rz = (pin[3 * j + 2] - qz) / RADIUS;

        float sq = rx * rx + ry * ry + rz * rz;
        float p1m = 1.0f - sq;
        float win = p1m * p1m * p1m;
        win = fminf(fmaxf(win, 0.f), 1.f);

        float nrm  = sqrtf(sq);
        float rxy2 = rx * rx + ry * ry;
        bool  polar = (1.25f * rz * rz) > rxy2;
        float s_pol = sqrtf(3.0f * nrm / (nrm + fabsf(rz) + EPS));
        float s_eq  = nrm / sqrtf(rxy2 + EPS);
        float xc = polar ? s_pol * rx : s_eq * rx;
        float yc = polar ? s_pol * ry : s_eq * ry;
        float zc = polar ? fsign(rz) * nrm : 1.5f * rz * s_eq;
        if (sq < 1e-12f) { xc = 0.f; yc = 0.f; zc = 0.f; }

        float rxy = sqrtf(xc * xc + yc * yc);
        float sx = (fabsf(xc) < EPS) ? EPS : xc;
        float sy = (fabsf(yc) < EPS) ? EPS : yc;
        float u1 = fsign(xc) * rxy;
        float v1 = u1 * FP * atanf(yc / sx);
        float v2 = fsign(yc) * rxy;
        float u2 = v2 * FP * atanf(xc / sy);
        float u, v;
        if (fabsf(xc) >= fabsf(yc)) { u = u1; v = v1; } else { u = u2; v = v2; }
        if (rxy < EPS) { u = 0.f; v = 0.f; }

        float gx = fminf(fmaxf((u  + 1.0f) * 0.5f * (float)(KS - 1), 0.f), (float)(KS - 1));
        float gy = fminf(fmaxf((v  + 1.0f) * 0.5f * (float)(KS - 1), 0.f), (float)(KS - 1));
        float gz = fminf(fmaxf((zc + 1.0f) * 0.5f * (float)(KS - 1), 0.f), (float)(KS - 1));
        int ix = min((int)floorf(gx), KS - 2);
        int iy = min((int)floorf(gy), KS - 2);
        int iz = min((int)floorf(gz), KS - 2);
        float tx = gx - (float)ix, ty = gy - (float)iy, tz = gz - (float)iz;

        int slot = i * KMAX + k;
        idx_out[slot]  = j;
        cell_out[slot] = (iz * KS + iy) * KS + ix;

        float wx[2] = {1.f - tx, tx};
        float wy[2] = {1.f - ty, ty};
        float wz[2] = {1.f - tz, tz};
        float* cf = coef_out + (size_t)slot * 8;
        #pragma unroll
        for (int dx = 0; dx < 2; dx++)
            #pragma unroll
            for (int dy = 0; dy < 2; dy++)
                #pragma unroll
                for (int dz = 0; dz < 2; dz++)
                    cf[dx * 4 + dy * 2 + dz] = wx[dx] * wy[dy] * wz[dz] * win;
    }
}

// ---------------------------------------------------------------------------
// convertW: build fp16 transposed weights Wt[n][k] for both HMMA layers.
// ---------------------------------------------------------------------------
__global__ void convertW(const float* __restrict__ c1w, const float* __restrict__ d1w,
                         const float* __restrict__ c2w, const float* __restrict__ d2w) {
    __shared__ float s[32][65];
    int t = blockIdx.x;
    const float *Wa, *Wb;
    __half* Wt;
    int K, Ka, k0;
    if (t < K1TOT / 32) {
        k0 = t * 32; K = K1TOT; Ka = 6144; Wa = c1w; Wb = d1w; Wt = g_Wt1;
    } else {
        k0 = (t - K1TOT / 32) * 32; K = K2TOT; Ka = 4096; Wa = c2w; Wb = d2w; Wt = g_Wt2;
    }
    int tid = threadIdx.x;
    #pragma unroll
    for (int i = 0; i < 8; i++) {
        int idx = tid + i * 256;          // 0..2047
        int row = idx >> 6;               // k offset 0..31
        int col = idx & 63;               // n
        int k = k0 + row;
        float v = (k < Ka) ? Wa[(size_t)k * 64 + col] : Wb[(size_t)(k - Ka) * 64 + col];
        s[row][col] = v;
    }
    __syncthreads();
    #pragma unroll
    for (int i = 0; i < 8; i++) {
        int idx = tid + i * 256;
        int n  = idx >> 5;                // 0..63
        int kk = idx & 31;
        Wt[(size_t)n * K + k0 + kk] = __float2half_rn(s[kk][n]);
    }
}

// ---------------------------------------------------------------------------
// prep: ff = [1,vel]; x96[:,64:96] = ff @ d0_w + d0_b
// ---------------------------------------------------------------------------
__global__ void prep_kernel(const float* __restrict__ vel,
                            const float* __restrict__ d0_w, const float* __restrict__ d0_b) {
    int i = blockIdx.x * blockDim.x + threadIdx.x;
    if (i >= NQ) return;
    float f1 = vel[i * 3 + 0], f2 = vel[i * 3 + 1], f3 = vel[i * 3 + 2];
    g_ff[i * 4 + 0] = 1.0f;
    g_ff[i * 4 + 1] = f1;
    g_ff[i * 4 + 2] = f2;
    g_ff[i * 4 + 3] = f3;
    #pragma unroll 8
    for (int o = 0; o < 32; o++) {
        g_x96[i * 96 + 64 + o] = d0_w[o] + f1 * d0_w[32 + o] + f2 * d0_w[64 + o]
                                 + f3 * d0_w[96 + o] + d0_b[o];
    }
}

// ---------------------------------------------------------------------------
// Merged first-block scatter: y=0 fluid/ff (F=4), y=1 box/box_feats (F=3).
// ---------------------------------------------------------------------------
__global__ void scatter_first(const float* __restrict__ box_feats) {
    int pass = blockIdx.y;
    const int F = pass ? 3 : 4;
    const int nF = 64 * F;
    const float* feats = pass ? box_feats : g_ff;
    const int* cnt  = pass ? g_ocnt  : g_fcnt;
    const int* nidx = pass ? g_oidx  : g_fidx;
    const int* ncel = pass ? g_ocell : g_fcell;
    const float* ncoef = pass ? g_ocoef : g_fcoef;
    __half* dst = g_S + (pass ? (size_t)NQ * 256 : 0);
    int ldS = pass ? 192 : 256;

    int i = blockIdx.x;
    extern __shared__ float shS[];            // 32 * nF floats (<= 32KB)
    __shared__ float shC[KMAX * 8];
    __shared__ int   shI[KMAX];
    __shared__ int   shCe[KMAX];
    int tid = threadIdx.x;
    const int NT = 128;

    for (int q = tid; q < 32 * nF; q += NT) shS[q] = 0.f;
    int c = cnt[i];
    for (int q = tid; q < c; q += NT) {
        shI[q]  = nidx[i * KMAX + q];
        shCe[q] = ncel[i * KMAX + q];
    }
    for (int q = tid; q < c * 8; q += NT)
        shC[q] = ncoef[(size_t)i * KMAX * 8 + q];
    __syncthreads();

    {
        int f = tid % F;
        int s = tid / F;
        if (s < 32) {
            int k0 = (c * s) / 32;
            int k1 = (c * (s + 1)) / 32;
            float* my = shS + s * nF;
            const int OFF[8] = {0, 16, 4, 20, 1, 17, 5, 21};
            for (int k = k0; k < k1; k++) {
                int j = shI[k];
                float vv = feats[(size_t)j * F + f];
                int base = shCe[k] * F + f;
                #pragma unroll
                for (int cc = 0; cc < 8; cc++)
                    my[base + OFF[cc] * F] += shC[k * 8 + cc] * vv;
            }
        }
    }
    __syncthreads();

    __half* drow = dst + (size_t)i * ldS;
    for (int q = tid * 2; q < nF; q += NT * 2) {
        float v0 = shS[q], v1 = shS[q + 1];
        #pragma unroll
        for (int s = 1; s < 32; s++) { v0 += shS[s * nF + q]; v1 += shS[s * nF + q + 1]; }
        *(__half2*)(drow + q) = __floats2half2_rn(v0, v1);
    }
}

// ---------------------------------------------------------------------------
// Merged 32-col GEMM pair: y=0 cf (K=256), y=1 co (K=192). Writes g_x96.
// ---------------------------------------------------------------------------
__global__ void gemm32_pair(const float* __restrict__ cf_w, const float* __restrict__ cf_b,
                            const float* __restrict__ co_w, const float* __restrict__ co_b) {
    int pass = blockIdx.y;
    int K = pass ? 192 : 256;
    const __half* A = g_S + (pass ? (size_t)NQ * 256 : 0);
    const float* W = pass ? co_w : cf_w;
    const float* b = pass ? co_b : cf_b;
    int ooff = pass ? 0 : 32;

    extern __shared__ float sW[];   // 32 * (K+1)
    int tid = threadIdx.x;
    int KP = K + 1;
    for (int q = tid; q < K * 32; q += blockDim.x) {
        int k = q >> 5, o = q & 31;
        sW[o * KP + k] = W[q];
    }
    __syncthreads();

    int warp = blockIdx.x * 8 + (tid >> 5);
    int lane = tid & 31;
    if (warp >= NQ) return;
    const __half* Ar = A + (size_t)warp * K;

    float acc[32];
    #pragma unroll
    for (int o = 0; o < 32; o++) acc[o] = 0.f;

    for (int k = lane * 2; k < K; k += 64) {
        float2 a = __half22float2(*(const __half2*)(Ar + k));
        #pragma unroll
        for (int o = 0; o < 32; o++)
            acc[o] += a.x * sW[o * KP + k] + a.y * sW[o * KP + k + 1];
    }

    float myv = 0.f;
    #pragma unroll
    for (int o = 0; o < 32; o++) {
        float v = acc[o];
        v += __shfl_xor_sync(0xffffffffu, v, 16);
        v += __shfl_xor_sync(0xffffffffu, v, 8);
        v += __shfl_xor_sync(0xffffffffu, v, 4);
        v += __shfl_xor_sync(0xffffffffu, v, 2);
        v += __shfl_xor_sync(0xffffffffu, v, 1);
        if (lane == o) myv = v;
    }
    g_x96[(size_t)warp * 96 + ooff + lane] = myv + b[lane];
}

// ---------------------------------------------------------------------------
// Tensor-core scatter: S_row[64,F] = CoefDense[64,80] @ NF[80,F] per particle.
// k-loop dynamically bounded at climit = ceil16(c): zero-fill and MMA only
// touch columns [0, climit). Columns [c, climit) are zeroed, so results match.
// ---------------------------------------------------------------------------
#define PA 82   // smem pitch in halves (41 words)

template <int F>
__global__ void scatter_mma(const int* __restrict__ cnt, const int* __restrict__ nidx,
                            const int* __restrict__ ncell, const float* __restrict__ ncoef,
                            const float* __restrict__ feats,
                            __half* __restrict__ Sout, int ldS) {
    __shared__ __half sA[64 * PA];      // coef dense [cell][k]
    __shared__ __half sB[F * PA];       // feats transposed [f][k]
    __shared__ float shC[KMAX * 8];
    __shared__ int   shI[KMAX];

    int i = blockIdx.x;
    int tid = threadIdx.x;
    int warp = tid >> 5, lane = tid & 31;
    int g = lane >> 2, tq = lane & 3;

    int c = cnt[i];
    int climit = (c + 15) & ~15;        // MMA k-range (multiple of 16, <= 80)
    int words = climit >> 1;            // half2 words per row to zero

    // zero only used columns of both operands
    unsigned* za = (unsigned*)sA;
    unsigned* zb = (unsigned*)sB;
    for (int q = tid; q < 64 * words; q += 128) {
        int r = q / words, w = q - r * words;
        za[r * (PA / 2) + w] = 0u;
    }
    for (int q = tid; q < F * words; q += 128) {
        int r = q / words, w = q - r * words;
        zb[r * (PA / 2) + w] = 0u;
    }

    for (int q = tid; q < c; q += 128) shI[q] = nidx[i * KMAX + q];
    for (int q = tid; q < c * 8; q += 128) shC[q] = ncoef[(size_t)i * KMAX * 8 + q];
    __syncthreads();

    // build A: 8 corner coefs per neighbor column
    {
        const int OFF[8] = {0, 16, 4, 20, 1, 17, 5, 21};
        __shared__ int shCe[KMAX];
        for (int q = tid; q < c; q += 128) shCe[q] = ncell[i * KMAX + q];
        __syncthreads();
        for (int t = tid; t < c * 8; t += 128) {
            int k = t >> 3, cc = t & 7;
            sA[(shCe[k] + OFF[cc]) * PA + k] = __float2half_rn(shC[t]);
        }
    }

    // gather B: NFt[f][k] = relu(feats[shI[k]][f])
    for (int k = warp; k < c; k += 4) {
        const float* fr = feats + (size_t)shI[k] * F;
        #pragma unroll
        for (int f = lane; f < F; f += 32)
            sB[f * PA + k] = __float2half_rn(fmaxf(fr[f], 0.f));
    }
    __syncthreads();

    float4 acc[F / 8];
    #pragma unroll
    for (int nj = 0; nj < F / 8; nj++) acc[nj] = make_float4(0.f, 0.f, 0.f, 0.f);

    for (int ks = 0; ks < climit; ks += 16) {
        int rbase = (warp * 16 + g) * PA + ks + 2 * tq;
        unsigned a0 = *(const unsigned*)&sA[rbase];
        unsigned a1 = *(const unsigned*)&sA[rbase + 8 * PA];
        unsigned a2 = *(const unsigned*)&sA[rbase + 8];
        unsigned a3 = *(const unsigned*)&sA[rbase + 8 * PA + 8];
        #pragma unroll
        for (int nj = 0; nj < F / 8; nj++) {
            int nbase = (nj * 8 + g) * PA + ks + 2 * tq;
            unsigned b0 = *(const unsigned*)&sB[nbase];
            unsigned b1 = *(const unsigned*)&sB[nbase + 8];
            mma16816(acc[nj], a0, a1, a2, a3, b0, b1);
        }
    }

    __half* dst = Sout + (size_t)i * ldS;
    int r0 = warp * 16 + g, r1 = r0 + 8;
    #pragma unroll
    for (int nj = 0; nj < F / 8; nj++) {
        int col = nj * 8 + 2 * tq;
        *(__half2*)(dst + r0 * F + col) = __floats2half2_rn(acc[nj].x, acc[nj].y);
        *(__half2*)(dst + r1 * F + col) = __floats2half2_rn(acc[nj].z, acc[nj].w);
    }
    if (tid < F)
        dst[64 * F + tid] = __float2half_rn(fmaxf(feats[(size_t)i * F + tid], 0.f));
}

// ---------------------------------------------------------------------------
// HMMA GEMM with split-K: grid (ceil(M/64), SPLITK). Raw partials to part.
// ---------------------------------------------------------------------------
#define PITCH 40

__global__ void gemm_hmma_sk(const __half* __restrict__ A, int M, int K,
                             const __half* __restrict__ Wt,
                             float* __restrict__ part) {
    __shared__ __half sA[2][64 * PITCH];
    __shared__ __half sB[2][64 * PITCH];

    int tid = threadIdx.x;
    int warp = tid >> 5, lane = tid & 31;
    int g = lane >> 2, tq = lane & 3;
    int wm = (warp & 1) * 32, wn = (warp >> 1) * 32;
    int bm = blockIdx.x * 64;

    int nt = K / 32;
    int tps = (nt + SPLITK - 1) / SPLITK;
    int t0 = blockIdx.y * tps;
    int t1 = min(t0 + tps, nt);
    float* out = part + (size_t)blockIdx.y * M * 64;

    int c0 = tid * 2, c1 = c0 + 1;
    int rA0 = c0 >> 2, ch0 = c0 & 3;
    int rA1 = c1 >> 2, ch1 = c1 & 3;
    bool ok0 = (bm + rA0) < M, ok1 = (bm + rA1) < M;
    const __half* Ab0 = A + (size_t)(bm + rA0) * K + ch0 * 8;
    const __half* Ab1 = A + (size_t)(bm + rA1) * K + ch1 * 8;
    const __half* Wb0 = Wt + (size_t)rA0 * K + ch0 * 8;
    const __half* Wb1 = Wt + (size_t)rA1 * K + ch1 * 8;

    float4 acc[2][4];
    #pragma unroll
    for (int i = 0; i < 2; i++)
        #pragma unroll
        for (int j = 0; j < 4; j++) acc[i][j] = make_float4(0.f, 0.f, 0.f, 0.f);

    const uint4 Z = make_uint4(0u, 0u, 0u, 0u);
    uint4 ra0, ra1, rb0, rb1;

    {
        int kt = t0 * 32;
        ra0 = ok0 ? *(const uint4*)(Ab0 + kt) : Z;
        ra1 = ok1 ? *(const uint4*)(Ab1 + kt) : Z;
        rb0 = *(const uint4*)(Wb0 + kt);
        rb1 = *(const uint4*)(Wb1 + kt);
    }
    *(uint4*)&sA[0][rA0 * PITCH + ch0 * 8] = ra0;
    *(uint4*)&sA[0][rA1 * PITCH + ch1 * 8] = ra1;
    *(uint4*)&sB[0][rA0 * PITCH + ch0 * 8] = rb0;
    *(uint4*)&sB[0][rA1 * PITCH + ch1 * 8] = rb1;
    __syncthreads();

    for (int t = t0; t < t1; t++) {
        int cur = (t - t0) & 1;
        if (t + 1 < t1) {
            int kt = (t + 1) * 32;
            ra0 = ok0 ? *(const uint4*)(Ab0 + kt) : Z;
            ra1 = ok1 ? *(const uint4*)(Ab1 + kt) : Z;
            rb0 = *(const uint4*)(Wb0 + kt);
            rb1 = *(const uint4*)(Wb1 + kt);
        }

        const __half* cA = sA[cur];
        const __half* cB = sB[cur];
        #pragma unroll
        for (int ks = 0; ks < 32; ks += 16) {
            unsigned af[2][4], bf[4][2];
            #pragma unroll
            for (int mi = 0; mi < 2; mi++) {
                int rbase = (wm + mi * 16 + g) * PITCH + ks + 2 * tq;
                af[mi][0] = *(const unsigned*)&cA[rbase];
                af[mi][1] = *(const unsigned*)&cA[rbase + 8 * PITCH];
                af[mi][2] = *(const unsigned*)&cA[rbase + 8];
                af[mi][3] = *(const unsigned*)&cA[rbase + 8 * PITCH + 8];
            }
            #pragma unroll
            for (int nj = 0; nj < 4; nj++) {
                int nbase = (wn + nj * 8 + g) * PITCH + ks + 2 * tq;
                bf[nj][0] = *(const unsigned*)&cB[nbase];
                bf[nj][1] = *(const unsigned*)&cB[nbase + 8];
            }
            #pragma unroll
            for (int mi = 0; mi < 2; mi++)
                #pragma unroll
                for (int nj = 0; nj < 4; nj++)
                    mma16816(acc[mi][nj], af[mi][0], af[mi][1], af[mi][2], af[mi][3],
                             bf[nj][0], bf[nj][1]);
        }

        if (t + 1 < t1) {
            int nxt = cur ^ 1;
            *(uint4*)&sA[nxt][rA0 * PITCH + ch0 * 8] = ra0;
            *(uint4*)&sA[nxt][rA1 * PITCH + ch1 * 8] = ra1;
            *(uint4*)&sB[nxt][rA0 * PITCH + ch0 * 8] = rb0;
            *(uint4*)&sB[nxt][rA1 * PITCH + ch1 * 8] = rb1;
            __syncthreads();
        }
    }

    #pragma unroll
    for (int mi = 0; mi < 2; mi++) {
        int r0 = bm + wm + mi * 16 + g;
        int r1 = r0 + 8;
        #pragma unroll
        for (int nj = 0; nj < 4; nj++) {
            int col = wn + nj * 8 + 2 * tq;
            float4 d = acc[mi][nj];
            if (r0 < M) *(float2*)&out[(size_t)r0 * 64 + col] = make_float2(d.x, d.y);
            if (r1 < M) *(float2*)&out[(size_t)r1 * 64 + col] = make_float2(d.z, d.w);
        }
    }
}

// ---------------------------------------------------------------------------
// combine4: out = sum(4 partials) + b1 + b2 (+ res)
// ---------------------------------------------------------------------------
__global__ void combine4(const float* __restrict__ part,
                         const float* __restrict__ b1, const float* __restrict__ b2,
                         const float* __restrict__ res, float* __restrict__ out, int M) {
    int idx = blockIdx.x * blockDim.x + threadIdx.x;
    if (idx >= M * 64) return;
    int c = idx & 63;
    size_t st = (size_t)M * 64;
    float v = part[idx] + part[st + idx] + part[2 * st + idx] + part[3 * st + idx]
              + b1[c] + b2[c];
    if (res) v += res[idx];
    out[idx] = v;
}

// ---------------------------------------------------------------------------
// Small-O GEMM (final layer), fp16 A, transposed padded W cache [O][K+1].
// ---------------------------------------------------------------------------
template <int O>
__global__ void gemm_small(const __half* __restrict__ A, int lda, int M,
                           int K1, const float* __restrict__ W1,
                           int K2, const float* __restrict__ W2,
                           const float* __restrict__ bias1, const float* __restrict__ bias2,
                           float* __restrict__ out, int ldo, int ooff, float scale) {
    extern __shared__ float sW[];   // O * (K+1), transposed
    int tid = threadIdx.x;
    int K = K1 + K2;
    int KP = K + 1;
    for (int q = tid; q < K1 * O; q += blockDim.x) {
        int k = q / O, o = q - k * O;
        sW[o * KP + k] = W1[q];
    }
    for (int q = tid; q < K2 * O; q += blockDim.x) {
        int k = q / O, o = q - k * O;
        sW[o * KP + K1 + k] = W2[q];
    }
    __syncthreads();

    int warp = blockIdx.x * (blockDim.x >> 5) + (tid >> 5);
    int lane = tid & 31;
    if (warp >= M) return;
    const __half* Ar = A + (size_t)warp * lda;

    float acc[O];
    #pragma unroll
    for (int o = 0; o < O; o++) acc[o] = 0.f;

    for (int k = lane * 2; k < K; k += 64) {
        float2 a = __half22float2(*(const __half2*)(Ar + k));
        #pragma unroll
        for (int o = 0; o < O; o++)
            acc[o] += a.x * sW[o * KP + k] + a.y * sW[o * KP + k + 1];
    }

    float myv = 0.f;
    #pragma unroll
    for (int o = 0; o < O; o++) {
        float v = acc[o];
        v += __shfl_xor_sync(0xffffffffu, v, 16);
        v += __shfl_xor_sync(0xffffffffu, v, 8);
        v += __shfl_xor_sync(0xffffffffu, v, 4);
        v += __shfl_xor_sync(0xffffffffu, v, 2);
        v += __shfl_xor_sync(0xffffffffu, v, 1);
        if (lane == o) myv = v;
    }
    if (lane < O) {
        float r = myv + (bias1 ? bias1[lane] : 0.f) + (bias2 ? bias2[lane] : 0.f);
        out[(size_t)warp * ldo + ooff + lane] = r * scale;
    }
}

// ---------------------------------------------------------------------------
// Host launch
// ---------------------------------------------------------------------------
template <typename T>
static T* symaddr(const void* sym) {
    void* p = nullptr;
    cudaGetSymbolAddress(&p, sym);
    return (T*)p;
}

extern "C" void kernel_launch(void* const* d_in, const int* in_sizes, int n_in,
                              void* d_out, int out_size) {
    cudaFuncSetAttribute(gemm_small<3>, cudaFuncAttributeMaxDynamicSharedMemorySize, 64 * 1024);

    const float* pos       = (const float*)d_in[0];
    const float* vel       = (const float*)d_in[1];
    const float* box       = (const float*)d_in[2];
    const float* box_feats = (const float*)d_in[3];
    const float* cf_w = (const float*)d_in[4];
    const float* cf_b = (const float*)d_in[5];
    const float* co_w = (const float*)d_in[6];
    const float* co_b = (const float*)d_in[7];
    const float* d0_w = (const float*)d_in[8];
    const float* d0_b = (const float*)d_in[9];
    const float* c1_w = (const float*)d_in[10];
    const float* c1_b = (const float*)d_in[11];
    const float* d1_w = (const float*)d_in[12];
    const float* d1_b = (const float*)d_in[13];
    const float* c2_w = (const float*)d_in[14];
    const float* c2_b = (const float*)d_in[15];
    const float* d2_w = (const float*)d_in[16];
    const float* d2_b = (const float*)d_in[17];
    const float* c3_w = (const float*)d_in[18];
    const float* c3_b = (const float*)d_in[19];
    const float* d3_w = (const float*)d_in[20];
    const float* d3_b = (const float*)d_in[21];
    float* out = (float*)d_out;

    __half* S   = symaddr<__half>(g_S);
    float* x96  = symaddr<float>(g_x96);
    float* ya   = symaddr<float>(g_ya);
    float* yb   = symaddr<float>(g_yb);
    float* part = symaddr<float>(g_part);
    __half* Wt1 = symaddr<__half>(g_Wt1);
    __half* Wt2 = symaddr<__half>(g_Wt2);
    int*   fcnt  = symaddr<int>(g_fcnt);
    int*   fidx  = symaddr<int>(g_fidx);
    int*   fcell = symaddr<int>(g_fcell);
    float* fcoef = symaddr<float>(g_fcoef);

    const int M = NQ;

    // 0-2) hash grids
    dim3 gh((NQ + 255) / 256, 2);
    grid_hist2<<<gh, 256>>>(pos, box);                          // idx 0
    grid_scan2<<<2, NCELLS>>>();                                // idx 1
    grid_fill2<<<gh, 256>>>(pos, box);                          // idx 2

    // 3) neighbor search (ncu profiled slot)
    dim3 gn(NQ, 2);
    nbr_grid2<<<gn, 128>>>(pos, box);                           // idx 3

    // 4-5) weight convert + prep (independent)
    convertW<<<(K1TOT + K2TOT) / 32, 256>>>(c1_w, d1_w, c2_w, d2_w);
    prep_kernel<<<(NQ + 255) / 256, 256>>>(vel, d0_w, d0_b);

    // 6-7) first block (merged): x96 = [a_co | a_cf | a_d0]
    dim3 gs(NQ, 2);
    scatter_first<<<gs, 128, 32 * 64 * 4 * 4>>>(box_feats);
    dim3 gp((M + 7) / 8, 2);
    gemm32_pair<<<gp, 256, 257 * 32 * 4>>>(cf_w, cf_b, co_w, co_b);

    dim3 gg((M + 63) / 64, SPLITK);

    // 8-10) layer 1: ya = S1 @ [c1_w; d1_w] + c1_b + d1_b
    scatter_mma<96><<<NQ, 128>>>(fcnt, fidx, fcell, fcoef, x96, S, K1TOT);
    gemm_hmma_sk<<<gg, 128>>>(S, M, K1TOT, Wt1, part);
    combine4<<<(M * 64 + 255) / 256, 256>>>(part, c1_b, d1_b, nullptr, ya, M);

    // 11-13) layer 2: yb = S2 @ [c2_w; d2_w] + c2_b + d2_b + ya
    scatter_mma<64><<<NQ, 128>>>(fcnt, fidx, fcell, fcoef, ya, S, K2TOT);
    gemm_hmma_sk<<<gg, 128>>>(S, M, K2TOT, Wt2, part);
    combine4<<<(M * 64 + 255) / 256, 256>>>(part, c2_b, d2_b, ya, yb, M);

    // 14-15) layer 3: out = (S3 @ [c3_w; d3_w] + c3_b + d3_b) / 128
    scatter_mma<64><<<NQ, 128>>>(fcnt, fidx, fcell, fcoef, yb, S, K2TOT);
    gemm_small<3><<<(M + 7) / 8, 256, 4161 * 3 * 4>>>(S, K2TOT, M, 4096, c3_w, 64, d3_w, c3_b, d3_b, out, 3, 0, 1.0f / 128.0f);
}